// round 12
// baseline (speedup 1.0000x reference)
#include <cuda_runtime.h>
#include <cuda_fp16.h>
#include <math.h>
#include <stdint.h>

// ---------------- problem constants ----------------
#define Bq_ 4
#define Sq_ 1024
#define Vq_ 50257
#define VPAD_ 50304
#define Dq_ 768
#define Hq_ 3072
#define NHq_ 12
#define DHq_ 64
#define Lq_ 12
#define Mq_ (Bq_*Sq_)   // 4096 rows

typedef __half f16;

#define WSQ (768UL*768UL)
#define WSH (768UL*3072UL)
#define LWBLK (4UL*WSQ + 2UL*WSH)
#define WOUT_OFF (LWBLK*12UL)
#define WTOT (WOUT_OFF + (size_t)VPAD_*Dq_)

// ---------------- scratch (device globals; no allocs allowed) ----------------
__device__ float g_h[Mq_*Dq_];
__device__ float g_p[3UL*Mq_*Dq_];          // split-K3 partial planes
__device__ f16 g_a[Mq_*Dq_];
__device__ f16 g_q[Mq_*Dq_];
__device__ f16 g_k[Mq_*Dq_];
__device__ f16 g_v[Mq_*Dq_];
__device__ f16 g_o[Mq_*Dq_];
__device__ f16 g_f[Mq_*Hq_];
__device__ f16 g_whi[WTOT], g_wlo[WTOT];

// ---------------- helpers ----------------
__device__ __forceinline__ uint32_t s2u(const void* p) {
    return (uint32_t)__cvta_generic_to_shared(p);
}
__device__ __forceinline__ void cp16(uint32_t d, const void* s) {
    asm volatile("cp.async.cg.shared.global [%0], [%1], 16;\n" :: "r"(d), "l"(s) : "memory");
}
#define CP_COMMIT asm volatile("cp.async.commit_group;\n" ::: "memory")
#define CP_WAIT1  asm volatile("cp.async.wait_group 1;\n" ::: "memory")
#define CP_WAIT0  asm volatile("cp.async.wait_group 0;\n" ::: "memory")

__device__ __forceinline__ void ldsm4(uint32_t &r0, uint32_t &r1, uint32_t &r2, uint32_t &r3,
                                      uint32_t addr) {
    asm volatile("ldmatrix.sync.aligned.m8n8.x4.shared.b16 {%0,%1,%2,%3}, [%4];\n"
        : "=r"(r0), "=r"(r1), "=r"(r2), "=r"(r3) : "r"(addr));
}
__device__ __forceinline__ void ldsm4t(uint32_t &r0, uint32_t &r1, uint32_t &r2, uint32_t &r3,
                                       uint32_t addr) {
    asm volatile("ldmatrix.sync.aligned.m8n8.x4.trans.shared.b16 {%0,%1,%2,%3}, [%4];\n"
        : "=r"(r0), "=r"(r1), "=r"(r2), "=r"(r3) : "r"(addr));
}
__device__ __forceinline__ void mma_f16(float* c, uint32_t a0, uint32_t a1, uint32_t a2, uint32_t a3,
                                        uint32_t b0, uint32_t b1) {
    asm volatile("mma.sync.aligned.m16n8k16.row.col.f32.f16.f16.f32 "
        "{%0,%1,%2,%3},{%4,%5,%6,%7},{%8,%9},{%0,%1,%2,%3};\n"
        : "+f"(c[0]), "+f"(c[1]), "+f"(c[2]), "+f"(c[3])
        : "r"(a0), "r"(a1), "r"(a2), "r"(a3), "r"(b0), "r"(b1));
}
__device__ __forceinline__ void split2h(float x, f16& h, f16& l) {
    h = __float2half_rn(x);
    l = __float2half_rn(x - __half2float(h));
}
__device__ __forceinline__ uint32_t packh2(float a, float b) {
    __half2 t = __floats2half2_rn(a, b);
    return *(uint32_t*)&t;
}

// ---------------- weight transpose + split (batched) ----------------
template<bool WRITE_LO>
__device__ __forceinline__ void tsplit_body(const float* __restrict__ W, f16* __restrict__ hi,
                                            f16* __restrict__ lo, int K, int Nsrc) {
    __shared__ float tile[32][33];
    int k0 = blockIdx.y * 32, n0 = blockIdx.x * 32;
    int tx = threadIdx.x, ty = threadIdx.y;
    #pragma unroll
    for (int i = 0; i < 4; i++) {
        int k = k0 + ty + i * 8, n = n0 + tx;
        tile[ty + i * 8][tx] = (n < Nsrc) ? W[(long)k * Nsrc + n] : 0.f;
    }
    __syncthreads();
    #pragma unroll
    for (int i = 0; i < 4; i++) {
        int n = n0 + ty + i * 8, k = k0 + tx;
        float v = tile[tx][ty + i * 8];
        f16 h, l; split2h(v, h, l);
        hi[(long)n * K + k] = h;
        if (WRITE_LO) lo[(long)n * K + k] = l;
    }
}

// Wq, Wk, Wo -> 1-term (hi only); Wv -> 2-term
__global__ void tsplit_sq_kernel(const float* __restrict__ Wq, const float* __restrict__ Wk,
                                 const float* __restrict__ Wv, const float* __restrict__ Wo,
                                 f16* __restrict__ hi, f16* __restrict__ lo) {
    int z = blockIdx.z, layer = z >> 2, which = z & 3;
    const float* W = (which == 0 ? Wq : which == 1 ? Wk : which == 2 ? Wv : Wo) + (size_t)layer * WSQ;
    size_t off = (size_t)layer * LWBLK + (size_t)which * WSQ;
    if (which == 2)
        tsplit_body<true>(W, hi + off, lo + off, 768, 768);
    else
        tsplit_body<false>(W, hi + off, nullptr, 768, 768);
}
__global__ void tsplit_w1_kernel(const float* __restrict__ W1, f16* __restrict__ hi, f16* __restrict__ lo) {
    int layer = blockIdx.z;
    size_t off = (size_t)layer * LWBLK + 4 * WSQ;
    tsplit_body<true>(W1 + (size_t)layer * WSH, hi + off, lo + off, 768, Hq_);
}
__global__ void tsplit_w2_kernel(const float* __restrict__ W2, f16* __restrict__ hi, f16* __restrict__ lo) {
    int layer = blockIdx.z;
    size_t off = (size_t)layer * LWBLK + 4 * WSQ + WSH;
    tsplit_body<true>(W2 + (size_t)layer * WSH, hi + off, lo + off, Hq_, 768);
}
__global__ void tsplit_out_kernel(const float* __restrict__ W, f16* __restrict__ hi) {
    tsplit_body<false>(W, hi + WOUT_OFF, nullptr, 768, Vq_);
}

// ---------------- embedding ----------------
__global__ void embed_kernel(const int* __restrict__ x,
                             const float* __restrict__ tok,
                             const float* __restrict__ pos,
                             float* __restrict__ h) {
    int row = blockIdx.x;
    int s = row & (Sq_ - 1);
    int tid = x[row];
    const float* tp = tok + (long)tid * Dq_;
    const float* pp = pos + (long)s * Dq_;
    float* hp = h + (long)row * Dq_;
    for (int d = threadIdx.x; d < Dq_; d += 256)
        hp[d] = tp[d] + pp[d];
}

// ---------------- warp-per-row layernorm (+ optional partial-plane sum) ----------------
// block = 256 threads = 8 warps = 8 rows; lane handles 6 float4 chunks (24 elems).
// SUM: v = H + P0 + P1 + P2 (WRITEH: write back to H). Y = fp16 LN output.
template<bool SUM, bool WRITEH>
__global__ __launch_bounds__(256) void ln_warp_kernel(
    float* __restrict__ H,
    const float* __restrict__ P0, const float* __restrict__ P1, const float* __restrict__ P2,
    const float* __restrict__ w, const float* __restrict__ bb,
    f16* __restrict__ Y)
{
    int warp = threadIdx.x >> 5, lane = threadIdx.x & 31;
    long base = ((long)blockIdx.x * 8 + warp) * Dq_;

    float4 v[6];
    #pragma unroll
    for (int j = 0; j < 6; j++) {
        int idx = (lane + j * 32) * 4;
        float4 hv = *(const float4*)&H[base + idx];
        if (SUM) {
            float4 a0 = *(const float4*)&P0[base + idx];
            float4 a1 = *(const float4*)&P1[base + idx];
            float4 a2 = *(const float4*)&P2[base + idx];
            hv.x += a0.x + a1.x + a2.x;
            hv.y += a0.y + a1.y + a2.y;
            hv.z += a0.z + a1.z + a2.z;
            hv.w += a0.w + a1.w + a2.w;
            if (WRITEH) *(float4*)&H[base + idx] = hv;
        }
        v[j] = hv;
    }

    float s = 0.f;
    #pragma unroll
    for (int j = 0; j < 6; j++) s += v[j].x + v[j].y + v[j].z + v[j].w;
    #pragma unroll
    for (int o = 16; o > 0; o >>= 1) s += __shfl_xor_sync(0xffffffffu, s, o);
    float mean = s * (1.0f / Dq_);

    float q = 0.f;
    #pragma unroll
    for (int j = 0; j < 6; j++) {
        v[j].x -= mean; v[j].y -= mean; v[j].z -= mean; v[j].w -= mean;
        q += v[j].x * v[j].x + v[j].y * v[j].y + v[j].z * v[j].z + v[j].w * v[j].w;
    }
    #pragma unroll
    for (int o = 16; o > 0; o >>= 1) q += __shfl_xor_sync(0xffffffffu, q, o);
    float inv = rsqrtf(q * (1.0f / Dq_) + 1e-5f);

    #pragma unroll
    for (int j = 0; j < 6; j++) {
        int idx = (lane + j * 32) * 4;
        float4 wv = *(const float4*)&w[idx];
        float4 bv = *(const float4*)&bb[idx];
        uint2 outp;
        outp.x = packh2(v[j].x * inv * wv.x + bv.x, v[j].y * inv * wv.y + bv.y);
        outp.y = packh2(v[j].z * inv * wv.z + bv.z, v[j].w * inv * wv.w + bv.w);
        *(uint2*)&Y[base + idx] = outp;
    }
}

// ---------------- fp16 HMMA GEMM, 3-stage pipeline ----------------
// C = A[MxK](f16) * (Bh [+ Bl])^T + bias
// EPI: 0 = fp32 C+bias; 1 = GELU -> f16; 3 = f16 out; 4 = split-K3 fp32 partial plane
#define GEMM_SMEM (3 * 3 * 128 * 40 * 2)   // 92160 max

template<int EPI, bool SWAP, int NTERMS>
__device__ __forceinline__ void gemm_body(
    const f16* __restrict__ A,
    const f16* __restrict__ Bhi, const f16* __restrict__ Blo,
    const float* __restrict__ bias,
    float* __restrict__ C, f16* __restrict__ C16,
    int K, int N, int Nout)
{
    const int ARR = 1 + NTERMS;
    extern __shared__ f16 sm[];
    uint32_t smb = s2u(sm);
    int tid = threadIdx.x;
    int bm = (SWAP ? blockIdx.x : blockIdx.y) * 128;
    int bn = (SWAP ? blockIdx.y : blockIdx.x) * 128;
    int warp = tid >> 5, lane = tid & 31;
    int wm = warp >> 2, wn = warp & 3;

    int kz = (EPI == 4) ? blockIdx.z : 0;
    int Keff = (EPI == 4) ? (K / 3) : K;
    long koff = (long)kz * Keff;

    float acc[4][4][4];
    #pragma unroll
    for (int i = 0; i < 4; i++)
        #pragma unroll
        for (int j = 0; j < 4; j++)
            #pragma unroll
            for (int k = 0; k < 4; k++) acc[i][j][k] = 0.f;

    const f16* srcs[3] = { A + (long)bm * K + koff, Bhi + (long)bn * K + koff,
                           (NTERMS == 2) ? Blo + (long)bn * K + koff : nullptr };

    auto issue = [&](int b, int kt) {
        int k0 = kt * 32;
        #pragma unroll
        for (int arr = 0; arr < ARR; arr++) {
            #pragma unroll
            for (int i = 0; i < 2; i++) {
                int ch = tid + i * 256;
                int row = ch >> 2, cg = ch & 3;
                uint32_t dst = smb + ((((b * ARR + arr) * 128 + row) * 40) + cg * 8) * 2;
                cp16(dst, srcs[arr] + (long)row * K + k0 + cg * 8);
            }
        }
    };

    int nk = Keff >> 5;
    issue(0, 0); CP_COMMIT;
    issue(1, 1); CP_COMMIT;

    int lrow = lane & 15, lcg = lane >> 4;

    for (int kt = 0; kt < nk; ++kt) {
        int cur = kt % 3;
        if (kt + 1 < nk) { CP_WAIT1; } else { CP_WAIT0; }
        __syncthreads();
        if (kt + 2 < nk) { issue((kt + 2) % 3, kt + 2); CP_COMMIT; }

        #pragma unroll
        for (int ks = 0; ks < 2; ++ks) {
            uint32_t af[4][4];
            #pragma unroll
            for (int mf = 0; mf < 4; mf++) {
                int row = wm * 64 + mf * 16 + lrow;
                int col = ks * 16 + lcg * 8;
                uint32_t a0 = smb + ((((cur * ARR + 0) * 128 + row) * 40) + col) * 2;
                ldsm4(af[mf][0], af[mf][1], af[mf][2], af[mf][3], a0);
            }
            uint32_t bh[2][4], bl[2][4];
            #pragma unroll
            for (int nf2 = 0; nf2 < 2; nf2++) {
                int row = wn * 32 + nf2 * 16 + lrow;
                int col = ks * 16 + lcg * 8;
                uint32_t b0 = smb + ((((cur * ARR + 1) * 128 + row) * 40) + col) * 2;
                ldsm4(bh[nf2][0], bh[nf2][1], bh[nf2][2], bh[nf2][3], b0);
                if (NTERMS == 2) {
                    uint32_t b1 = smb + ((((cur * ARR + 2) * 128 + row) * 40) + col) * 2;
                    ldsm4(bl[nf2][0], bl[nf2][1], bl[nf2][2], bl[nf2][3], b1);
                }
            }
            #pragma unroll
            for (int mf = 0; mf < 4; mf++)
                #pragma unroll
                for (int nf = 0; nf < 4; nf++) {
                    int g = nf >> 1, o = nf & 1;
                    mma_f16(acc[mf][nf], af[mf][0], af[mf][1], af[mf][2], af[mf][3],
                            bh[g][o], bh[g][o + 2]);
                }
            if (NTERMS == 2) {
                #pragma unroll
                for (int mf = 0; mf < 4; mf++)
                    #pragma unroll
                    for (int nf = 0; nf < 4; nf++) {
                        int g = nf >> 1, o = nf & 1;
                        mma_f16(acc[mf][nf], af[mf][0], af[mf][1], af[mf][2], af[mf][3],
                                bl[g][o], bl[g][o + 2]);
                    }
            }
        }
    }

    float* Cp = (EPI == 4) ? (C + (size_t)kz * Mq_ * (size_t)Nout) : C;

    int r = lane >> 2, c2 = (lane & 3) * 2;
    #pragma unroll
    for (int mf = 0; mf < 4; mf++) {
        #pragma unroll
        for (int nf = 0; nf < 4; nf++) {
            #pragma unroll
            for (int half2_ = 0; half2_ < 2; half2_++) {
                long row = bm + wm * 64 + mf * 16 + r + half2_ * 8;
                #pragma unroll
                for (int e = 0; e < 2; e++) {
                    int col = bn + wn * 32 + nf * 8 + c2 + e;
                    if (col < Nout) {
                        float v = acc[mf][nf][half2_ * 2 + e];
                        if (EPI == 4) {
                            if (kz == 0) v += bias[col];
                            Cp[row * (long)Nout + col] = v;
                        } else {
                            v += bias[col];
                            if (EPI == 1 || EPI == 3) {
                                if (EPI == 1)
                                    v = 0.5f * v * (1.f + erff(v * 0.70710678118654752f));
                                C16[row * N + col] = __float2half_rn(v);
                            } else {
                                Cp[row * (long)Nout + col] = v;
                            }
                        }
                    }
                }
            }
        }
    }
}

template<int EPI, bool SWAP, int NTERMS>
__global__ __launch_bounds__(256, 1) void gemm_kernel(
    const f16* __restrict__ A,
    const f16* __restrict__ Bhi, const f16* __restrict__ Blo,
    const float* __restrict__ bias,
    float* __restrict__ C, f16* __restrict__ C16,
    int K, int N, int Nout)
{
    gemm_body<EPI, SWAP, NTERMS>(A, Bhi, Blo, bias, C, C16, K, N, Nout);
}

// fused Q+K GEMMs (1-term weights), blockIdx.z: 0=Q, 1=K
__global__ __launch_bounds__(256, 1) void gemm_qk_kernel(
    const f16* __restrict__ A,
    const f16* __restrict__ whi,
    const float* __restrict__ bq, const float* __restrict__ bk,
    f16* __restrict__ q, f16* __restrict__ k)
{
    int z = blockIdx.z;
    const f16* Bh = whi + (size_t)z * WSQ;
    const float* bias = z ? bk : bq;
    f16* C16 = z ? k : q;
    gemm_body<3, false, 1>(A, Bh, nullptr, bias, nullptr, C16, Dq_, Dq_, Dq_);
}

// ---------------- HMMA flash attention, fp16, double-buffered, heavy-first ----------------
#define AT_STRIDE 72
#define AT_TILE (64 * AT_STRIDE)
#define ATTN_SMEM (5 * AT_TILE * 2)   // Q + 2x(K,V) = 46080

__global__ __launch_bounds__(128, 4) void attn_kernel(
    const f16* __restrict__ Qg, const f16* __restrict__ Kg, const f16* __restrict__ Vg,
    f16* __restrict__ O)
{
    extern __shared__ f16 asm_[];
    uint32_t smb = s2u(asm_);
    uint32_t sQ = smb;

    int t = threadIdx.x, warp = t >> 5, lane = t & 31;
    int qt = (int)gridDim.x - 1 - (int)blockIdx.x;   // LPT: heavy first
    int q0 = qt * 64, h = blockIdx.y, b = blockIdx.z;

    long rowbase = (long)(b * Sq_ + q0) * Dq_ + h * DHq_;

    auto issue_kv = [&](int buf, int jt) {
        uint32_t sK = smb + (1 + buf * 2) * AT_TILE * 2;
        uint32_t sV = sK + AT_TILE * 2;
        long kbase = (long)(b * Sq_ + jt * 64) * Dq_ + h * DHq_;
        #pragma unroll
        for (int i = 0; i < 4; i++) {
            int idx = t + i * 128;
            int row = idx >> 3, ch = idx & 7;
            uint32_t doff = (uint32_t)(row * AT_STRIDE + ch * 8) * 2;
            long goff = kbase + (long)row * Dq_ + ch * 8;
            cp16(sK + doff, Kg + goff);
            cp16(sV + doff, Vg + goff);
        }
    };

    #pragma unroll
    for (int i = 0; i < 4; i++) {
        int idx = t + i * 128;
        int row = idx >> 3, ch = idx & 7;
        uint32_t doff = (uint32_t)(row * AT_STRIDE + ch * 8) * 2;
        cp16(sQ + doff, Qg + rowbase + (long)row * Dq_ + ch * 8);
    }
    issue_kv(0, 0);
    CP_COMMIT;

    float m[2] = { -1e30f, -1e30f }, l[2] = { 0.f, 0.f };
    float oacc[8][4];
    #pragma unroll
    for (int i = 0; i < 8; i++)
        #pragma unroll
        for (int j = 0; j < 4; j++) oacc[i][j] = 0.f;

    int lrow = lane & 15, lcg = lane >> 4;
    int ntiles = q0 / 64 + 1;

    for (int it = 0; it < ntiles; ++it) {
        if (it + 1 < ntiles) { issue_kv((it + 1) & 1, it + 1); CP_COMMIT; CP_WAIT1; }
        else                 { CP_WAIT0; }
        __syncthreads();

        uint32_t sK = smb + (1 + (it & 1) * 2) * AT_TILE * 2;
        uint32_t sV = sK + AT_TILE * 2;
        int j0 = it * 64;

        float sacc[8][4];
        #pragma unroll
        for (int i = 0; i < 8; i++)
            #pragma unroll
            for (int j = 0; j < 4; j++) sacc[i][j] = 0.f;

        #pragma unroll
        for (int ks = 0; ks < 4; ++ks) {
            int acol = ks * 16 + lcg * 8;
            uint32_t qf[4];
            uint32_t qaddr = (uint32_t)((warp * 16 + lrow) * AT_STRIDE + acol) * 2;
            ldsm4(qf[0], qf[1], qf[2], qf[3], sQ + qaddr);
            uint32_t kf[4][4];
            #pragma unroll
            for (int kg = 0; kg < 4; ++kg) {
                uint32_t kaddr = (uint32_t)((kg * 16 + lrow) * AT_STRIDE + acol) * 2;
                ldsm4(kf[kg][0], kf[kg][1], kf[kg][2], kf[kg][3], sK + kaddr);
            }
            #pragma unroll
            for (int kg = 0; kg < 4; ++kg)
                #pragma unroll
                for (int o = 0; o < 2; ++o)
                    mma_f16(sacc[kg * 2 + o], qf[0], qf[1], qf[2], qf[3], kf[kg][o], kf[kg][o + 2]);
        }

        int r0loc = warp * 16 + (lane >> 2);
        bool diag = (j0 == q0);
        float mx[2] = { -1e30f, -1e30f };
        #pragma unroll
        for (int nf = 0; nf < 8; nf++) {
            #pragma unroll
            for (int i = 0; i < 4; i++) {
                float v = sacc[nf][i] * 0.125f;
                if (diag) {
                    int col = nf * 8 + (lane & 3) * 2 + (i & 1);
                    int row = r0loc + ((i >> 1) ? 8 : 0);
                    if (col > row) v = -1e30f;
                }
                sacc[nf][i] = v;
                mx[i >> 1] = fmaxf(mx[i >> 1], v);
            }
        }
        #pragma unroll
        for (int o = 1; o < 4; o <<= 1) {
            mx[0] = fmaxf(mx[0], __shfl_xor_sync(0xffffffffu, mx[0], o));
            mx[1] = fmaxf(mx[1], __shfl_xor_sync(0xffffffffu, mx[1], o));
        }
        float fac[2], sum[2] = { 0.f, 0.f };
        #pragma unroll
        for (int j = 0; j < 2; j++) {
            float mnew = fmaxf(m[j], mx[j]);
            fac[j] = __expf(m[j] - mnew);
            m[j] = mnew;
        }
        #pragma unroll
        for (int nf = 0; nf < 8; nf++) {
            #pragma unroll
            for (int i = 0; i < 4; i++) {
                float p = __expf(sacc[nf][i] - m[i >> 1]);
                sacc[nf][i] = p;
                sum[i >> 1] += p;
            }
        }
        #pragma unroll
        for (int o = 1; o < 4; o <<= 1) {
            sum[0] += __shfl_xor_sync(0xffffffffu, sum[0], o);
            sum[1] += __shfl_xor_sync(0xffffffffu, sum[1], o);
        }
        #pragma unroll
        for (int j = 0; j < 2; j++) l[j] = l[j] * fac[j] + sum[j];
        #pragma unroll
        for (int nf = 0; nf < 8; nf++) {
            oacc[nf][0] *= fac[0]; oacc[nf][1] *= fac[0];
            oacc[nf][2] *= fac[1]; oacc[nf][3] *= fac[1];
        }

        #pragma unroll
        for (int t2 = 0; t2 < 4; ++t2) {
            float* p0 = sacc[2 * t2];
            float* p1 = sacc[2 * t2 + 1];
            uint32_t pa[4];
            pa[0] = packh2(p0[0], p0[1]);
            pa[1] = packh2(p0[2], p0[3]);
            pa[2] = packh2(p1[0], p1[1]);
            pa[3] = packh2(p1[2], p1[3]);

            uint32_t vf[4][4];
            #pragma unroll
            for (int nd = 0; nd < 4; ++nd) {
                uint32_t vrow = (uint32_t)(t2 * 16 + ((lane >> 4) << 3) + (lane & 7));
                uint32_t vcol = (uint32_t)(nd * 16 + (((lane >> 3) & 1) << 3));
                uint32_t vaddr = (vrow * AT_STRIDE + vcol) * 2;
                ldsm4t(vf[nd][0], vf[nd][1], vf[nd][2], vf[nd][3], sV + vaddr);
            }
            #pragma unroll
            for (int nd = 0; nd < 4; ++nd)
                #pragma unroll
                for (int o = 0; o < 2; ++o)
                    mma_f16(oacc[nd * 2 + o], pa[0], pa[1], pa[2], pa[3], vf[nd][o], vf[nd][o + 2]);
        }
        __syncthreads();
    }

    float inv0 = 1.f / l[0], inv1 = 1.f / l[1];
    long row0 = (long)(b * Sq_ + q0 + warp * 16 + (lane >> 2));
    long row1 = row0 + 8;
    #pragma unroll
    for (int nf = 0; nf < 8; nf++) {
        int col = h * DHq_ + nf * 8 + (lane & 3) * 2;
        *(__half2*)&O[row0 * Dq_ + col] = __floats2half2_rn(oacc[nf][0] * inv0, oacc[nf][1] * inv0);
        *(__half2*)&O[row1 * Dq_ + col] = __floats2half2_rn(oacc[nf][2] * inv1, oacc[nf][3] * inv1);
    }
}

// ---------------- launcher ----------------
extern "C" void kernel_launch(void* const* d_in, const int* in_sizes, int n_in,
                              void* d_out, int out_size) {
    const int*   x    = (const int*)  d_in[0];
    const float* tok  = (const float*)d_in[1];
    const float* pos  = (const float*)d_in[2];
    const float* Wq   = (const float*)d_in[3];
    const float* bq   = (const float*)d_in[4];
    const float* Wk   = (const float*)d_in[5];
    const float* bk   = (const float*)d_in[6];
    const float* Wv   = (const float*)d_in[7];
    const float* bv   = (const float*)d_in[8];
    const float* Wo   = (const float*)d_in[9];
    const float* bo   = (const float*)d_in[10];
    const float* ln1w = (const float*)d_in[11];
    const float* ln1b = (const float*)d_in[12];
    const float* ln2w = (const float*)d_in[13];
    const float* ln2b = (const float*)d_in[14];
    const float* W1   = (const float*)d_in[15];
    const float* b1   = (const float*)d_in[16];
    const float* W2   = (const float*)d_in[17];
    const float* b2   = (const float*)d_in[18];
    const float* lnfw = (const float*)d_in[19];
    const float* lnfb = (const float*)d_in[20];
    const float* Wout = (const float*)d_in[21];
    const float* bout = (const float*)d_in[22];
    float* out = (float*)d_out;

    float *h, *p;
    f16 *a, *q, *k, *v, *o, *f, *whi, *wlo;
    cudaGetSymbolAddress((void**)&h, g_h);
    cudaGetSymbolAddress((void**)&p, g_p);
    cudaGetSymbolAddress((void**)&a, g_a);
    cudaGetSymbolAddress((void**)&q, g_q);
    cudaGetSymbolAddress((void**)&k, g_k);
    cudaGetSymbolAddress((void**)&v, g_v);
    cudaGetSymbolAddress((void**)&o, g_o);
    cudaGetSymbolAddress((void**)&f, g_f);
    cudaGetSymbolAddress((void**)&whi, g_whi);
    cudaGetSymbolAddress((void**)&wlo, g_wlo);
    float* p0 = p;
    float* p1 = p + (size_t)Mq_ * Dq_;
    float* p2 = p + 2 * (size_t)Mq_ * Dq_;

    cudaFuncSetAttribute((const void*)gemm_kernel<0,true,1>,  cudaFuncAttributeMaxDynamicSharedMemorySize, GEMM_SMEM);
    cudaFuncSetAttribute((const void*)gemm_kernel<1,false,2>, cudaFuncAttributeMaxDynamicSharedMemorySize, GEMM_SMEM);
    cudaFuncSetAttribute((const void*)gemm_kernel<3,false,2>, cudaFuncAttributeMaxDynamicSharedMemorySize, GEMM_SMEM);
    cudaFuncSetAttribute((const void*)gemm_kernel<4,false,1>, cudaFuncAttributeMaxDynamicSharedMemorySize, GEMM_SMEM);
    cudaFuncSetAttribute((const void*)gemm_kernel<4,false,2>, cudaFuncAttributeMaxDynamicSharedMemorySize, GEMM_SMEM);
    cudaFuncSetAttribute((const void*)gemm_qk_kernel, cudaFuncAttributeMaxDynamicSharedMemorySize, GEMM_SMEM);
    cudaFuncSetAttribute((const void*)attn_kernel, cudaFuncAttributeMaxDynamicSharedMemorySize, ATTN_SMEM);

    // ---- weight prep (batched) ----
    dim3 tb(32, 8);
    tsplit_sq_kernel<<<dim3(24, 24, 48), tb>>>(Wq, Wk, Wv, Wo, whi, wlo);
    tsplit_w1_kernel<<<dim3(Hq_ / 32, 24, 12), tb>>>(W1, whi, wlo);
    tsplit_w2_kernel<<<dim3(24, Hq_ / 32, 12), tb>>>(W2, whi, wlo);
    tsplit_out_kernel<<<dim3(VPAD_ / 32, 24), tb>>>(Wout, whi);

    embed_kernel<<<Mq_, 256>>>(x, tok, pos, h);

    dim3 gD(Dq_ / 128, Mq_ / 128);       // 6 x 32
    dim3 gQK(Dq_ / 128, Mq_ / 128, 2);   // Q + K, 1-term
    dim3 gDs3(Dq_ / 128, Mq_ / 128, 3);  // split-K3 grid for N=768
    dim3 gH(Hq_ / 128, Mq_ / 128);
    dim3 gVsw(Mq_ / 128, VPAD_ / 128);
    dim3 gAtt(Sq_ / 64, NHq_, Bq_);
    const int LNG = Mq_ / 8;             // 512 blocks, warp-per-row

    for (int i = 0; i < Lq_; ++i) {
        size_t off = (size_t)i * LWBLK;
        if (i == 0)
            ln_warp_kernel<false,false><<<LNG, 256>>>(h, nullptr, nullptr, nullptr, ln1w, ln1b, a);
        else
            ln_warp_kernel<true,true><<<LNG, 256>>>(h, p0, p1, p2, ln1w + i * Dq_, ln1b + i * Dq_, a);

        gemm_qk_kernel<<<gQK, 256, GEMM_SMEM>>>(a, whi + off, bq + i * Dq_, bk + i * Dq_, q, k);
        gemm_kernel<3,false,2><<<gD, 256, GEMM_SMEM>>>(a, whi + off + 2 * WSQ, wlo + off + 2 * WSQ,
            bv + i * Dq_, nullptr, v, Dq_, Dq_, Dq_);
        attn_kernel<<<gAtt, 128, ATTN_SMEM>>>(q, k, v, o);

        gemm_kernel<4,false,1><<<gDs3, 256, GEMM_SMEM>>>(o, whi + off + 3 * WSQ, nullptr,
            bo + i * Dq_, p, nullptr, Dq_, Dq_, Dq_);

        ln_warp_kernel<true,true><<<LNG, 256>>>(h, p0, p1, p2, ln2w + i * Dq_, ln2b + i * Dq_, a);

        gemm_kernel<1,false,2><<<gH, 256, GEMM_SMEM>>>(a, whi + off + 4 * WSQ, wlo + off + 4 * WSQ,
            b1 + i * Hq_, nullptr, f, Dq_, Hq_, Hq_);

        gemm_kernel<4,false,2><<<gDs3, 256, GEMM_SMEM>>>(f, whi + off + 4 * WSQ + WSH, wlo + off + 4 * WSQ + WSH,
            b2 + i * Dq_, p, nullptr, Hq_, Dq_, Dq_);
    }

    ln_warp_kernel<true,false><<<LNG, 256>>>(h, p0, p1, p2, lnfw, lnfb, a);
    gemm_kernel<0,true,1><<<gVsw, 256, GEMM_SMEM>>>(a, whi + WOUT_OFF, nullptr,
        bout, out, nullptr, Dq_, VPAD_, Vq_);
}

// round 13
// speedup vs baseline: 1.2726x; 1.2726x over previous
#include <cuda_runtime.h>
#include <cuda_fp16.h>
#include <math.h>
#include <stdint.h>

// ---------------- problem constants ----------------
#define Bq_ 4
#define Sq_ 1024
#define Vq_ 50257
#define VPAD_ 50304
#define Dq_ 768
#define Hq_ 3072
#define NHq_ 12
#define DHq_ 64
#define Lq_ 12
#define Mq_ (Bq_*Sq_)   // 4096 rows

typedef __half f16;

#define WSQ (768UL*768UL)
#define WSH (768UL*3072UL)
#define LWBLK (4UL*WSQ + 2UL*WSH)
#define WOUT_OFF (LWBLK*12UL)
#define WTOT (WOUT_OFF + (size_t)VPAD_*Dq_)

// ---------------- scratch (device globals; no allocs allowed) ----------------
__device__ float g_h[Mq_*Dq_];
__device__ float g_p[3UL*Mq_*Dq_];          // split-K3 partial planes
__device__ f16 g_a[Mq_*Dq_];
__device__ f16 g_q[Mq_*Dq_];
__device__ f16 g_k[Mq_*Dq_];
__device__ f16 g_v[Mq_*Dq_];
__device__ f16 g_o[Mq_*Dq_];
__device__ f16 g_f[Mq_*Hq_];
__device__ f16 g_whi[WTOT];

// ---------------- helpers ----------------
__device__ __forceinline__ uint32_t s2u(const void* p) {
    return (uint32_t)__cvta_generic_to_shared(p);
}
__device__ __forceinline__ void cp16(uint32_t d, const void* s) {
    asm volatile("cp.async.cg.shared.global [%0], [%1], 16;\n" :: "r"(d), "l"(s) : "memory");
}
#define CP_COMMIT asm volatile("cp.async.commit_group;\n" ::: "memory")
#define CP_WAIT1  asm volatile("cp.async.wait_group 1;\n" ::: "memory")
#define CP_WAIT0  asm volatile("cp.async.wait_group 0;\n" ::: "memory")

__device__ __forceinline__ void ldsm4(uint32_t &r0, uint32_t &r1, uint32_t &r2, uint32_t &r3,
                                      uint32_t addr) {
    asm volatile("ldmatrix.sync.aligned.m8n8.x4.shared.b16 {%0,%1,%2,%3}, [%4];\n"
        : "=r"(r0), "=r"(r1), "=r"(r2), "=r"(r3) : "r"(addr));
}
__device__ __forceinline__ void ldsm4t(uint32_t &r0, uint32_t &r1, uint32_t &r2, uint32_t &r3,
                                       uint32_t addr) {
    asm volatile("ldmatrix.sync.aligned.m8n8.x4.trans.shared.b16 {%0,%1,%2,%3}, [%4];\n"
        : "=r"(r0), "=r"(r1), "=r"(r2), "=r"(r3) : "r"(addr));
}
__device__ __forceinline__ void mma_f16(float* c, uint32_t a0, uint32_t a1, uint32_t a2, uint32_t a3,
                                        uint32_t b0, uint32_t b1) {
    asm volatile("mma.sync.aligned.m16n8k16.row.col.f32.f16.f16.f32 "
        "{%0,%1,%2,%3},{%4,%5,%6,%7},{%8,%9},{%0,%1,%2,%3};\n"
        : "+f"(c[0]), "+f"(c[1]), "+f"(c[2]), "+f"(c[3])
        : "r"(a0), "r"(a1), "r"(a2), "r"(a3), "r"(b0), "r"(b1));
}
__device__ __forceinline__ uint32_t packh2(float a, float b) {
    __half2 t = __floats2half2_rn(a, b);
    return *(uint32_t*)&t;
}

// ---------------- weight transpose (fp16, 1-term), batched ----------------
__device__ __forceinline__ void tsplit_body(const float* __restrict__ W, f16* __restrict__ hi,
                                            int K, int Nsrc) {
    __shared__ float tile[32][33];
    int k0 = blockIdx.y * 32, n0 = blockIdx.x * 32;
    int tx = threadIdx.x, ty = threadIdx.y;
    #pragma unroll
    for (int i = 0; i < 4; i++) {
        int k = k0 + ty + i * 8, n = n0 + tx;
        tile[ty + i * 8][tx] = (n < Nsrc) ? W[(long)k * Nsrc + n] : 0.f;
    }
    __syncthreads();
    #pragma unroll
    for (int i = 0; i < 4; i++) {
        int n = n0 + ty + i * 8, k = k0 + tx;
        hi[(long)n * K + k] = __float2half_rn(tile[tx][ty + i * 8]);
    }
}

__global__ void tsplit_sq_kernel(const float* __restrict__ Wq, const float* __restrict__ Wk,
                                 const float* __restrict__ Wv, const float* __restrict__ Wo,
                                 f16* __restrict__ hi) {
    int z = blockIdx.z, layer = z >> 2, which = z & 3;
    const float* W = (which == 0 ? Wq : which == 1 ? Wk : which == 2 ? Wv : Wo) + (size_t)layer * WSQ;
    size_t off = (size_t)layer * LWBLK + (size_t)which * WSQ;
    tsplit_body(W, hi + off, 768, 768);
}
__global__ void tsplit_w1_kernel(const float* __restrict__ W1, f16* __restrict__ hi) {
    int layer = blockIdx.z;
    size_t off = (size_t)layer * LWBLK + 4 * WSQ;
    tsplit_body(W1 + (size_t)layer * WSH, hi + off, 768, Hq_);
}
__global__ void tsplit_w2_kernel(const float* __restrict__ W2, f16* __restrict__ hi) {
    int layer = blockIdx.z;
    size_t off = (size_t)layer * LWBLK + 4 * WSQ + WSH;
    tsplit_body(W2 + (size_t)layer * WSH, hi + off, Hq_, 768);
}
__global__ void tsplit_out_kernel(const float* __restrict__ W, f16* __restrict__ hi) {
    tsplit_body(W, hi + WOUT_OFF, 768, Vq_);
}

// ---------------- embedding ----------------
__global__ void embed_kernel(const int* __restrict__ x,
                             const float* __restrict__ tok,
                             const float* __restrict__ pos,
                             float* __restrict__ h) {
    int row = blockIdx.x;
    int s = row & (Sq_ - 1);
    int tid = x[row];
    const float* tp = tok + (long)tid * Dq_;
    const float* pp = pos + (long)s * Dq_;
    float* hp = h + (long)row * Dq_;
    for (int d = threadIdx.x; d < Dq_; d += 256)
        hp[d] = tp[d] + pp[d];
}

// ---------------- warp-per-row layernorm (+ optional partial-plane sum) ----------------
template<bool SUM, bool WRITEH>
__global__ __launch_bounds__(256) void ln_warp_kernel(
    float* __restrict__ H,
    const float* __restrict__ P0, const float* __restrict__ P1, const float* __restrict__ P2,
    const float* __restrict__ w, const float* __restrict__ bb,
    f16* __restrict__ Y)
{
    int warp = threadIdx.x >> 5, lane = threadIdx.x & 31;
    long base = ((long)blockIdx.x * 8 + warp) * Dq_;

    float4 v[6];
    #pragma unroll
    for (int j = 0; j < 6; j++) {
        int idx = (lane + j * 32) * 4;
        float4 hv = *(const float4*)&H[base + idx];
        if (SUM) {
            float4 a0 = *(const float4*)&P0[base + idx];
            float4 a1 = *(const float4*)&P1[base + idx];
            float4 a2 = *(const float4*)&P2[base + idx];
            hv.x += a0.x + a1.x + a2.x;
            hv.y += a0.y + a1.y + a2.y;
            hv.z += a0.z + a1.z + a2.z;
            hv.w += a0.w + a1.w + a2.w;
            if (WRITEH) *(float4*)&H[base + idx] = hv;
        }
        v[j] = hv;
    }

    float s = 0.f;
    #pragma unroll
    for (int j = 0; j < 6; j++) s += v[j].x + v[j].y + v[j].z + v[j].w;
    #pragma unroll
    for (int o = 16; o > 0; o >>= 1) s += __shfl_xor_sync(0xffffffffu, s, o);
    float mean = s * (1.0f / Dq_);

    float q = 0.f;
    #pragma unroll
    for (int j = 0; j < 6; j++) {
        v[j].x -= mean; v[j].y -= mean; v[j].z -= mean; v[j].w -= mean;
        q += v[j].x * v[j].x + v[j].y * v[j].y + v[j].z * v[j].z + v[j].w * v[j].w;
    }
    #pragma unroll
    for (int o = 16; o > 0; o >>= 1) q += __shfl_xor_sync(0xffffffffu, q, o);
    float inv = rsqrtf(q * (1.0f / Dq_) + 1e-5f);

    #pragma unroll
    for (int j = 0; j < 6; j++) {
        int idx = (lane + j * 32) * 4;
        float4 wv = *(const float4*)&w[idx];
        float4 bv = *(const float4*)&bb[idx];
        uint2 outp;
        outp.x = packh2(v[j].x * inv * wv.x + bv.x, v[j].y * inv * wv.y + bv.y);
        outp.y = packh2(v[j].z * inv * wv.z + bv.z, v[j].w * inv * wv.w + bv.w);
        *(uint2*)&Y[base + idx] = outp;
    }
}

// ---------------- fp16 HMMA GEMM, 1-term, 3-stage pipeline ----------------
// C = A[MxK](f16) * Bh^T + bias
// EPI: 0 = fp32 C+bias; 1 = GELU -> f16; 3 = f16 out; 4 = split-K3 fp32 partial plane
#define GEMM_SMEM (3 * 2 * 128 * 40 * 2)   // 61440

template<int EPI, bool SWAP>
__device__ __forceinline__ void gemm_body(
    const f16* __restrict__ A,
    const f16* __restrict__ Bhi,
    const float* __restrict__ bias,
    float* __restrict__ C, f16* __restrict__ C16,
    int K, int N, int Nout)
{
    extern __shared__ f16 sm[];    // [3 buf][2 arr][128][40]
    uint32_t smb = s2u(sm);
    int tid = threadIdx.x;
    int bm = (SWAP ? blockIdx.x : blockIdx.y) * 128;
    int bn = (SWAP ? blockIdx.y : blockIdx.x) * 128;
    int warp = tid >> 5, lane = tid & 31;
    int wm = warp >> 2, wn = warp & 3;

    int kz = (EPI == 4) ? blockIdx.z : 0;
    int Keff = (EPI == 4) ? (K / 3) : K;
    long koff = (long)kz * Keff;

    float acc[4][4][4];
    #pragma unroll
    for (int i = 0; i < 4; i++)
        #pragma unroll
        for (int j = 0; j < 4; j++)
            #pragma unroll
            for (int k = 0; k < 4; k++) acc[i][j][k] = 0.f;

    const f16* srcs[2] = { A + (long)bm * K + koff, Bhi + (long)bn * K + koff };

    auto issue = [&](int b, int kt) {
        int k0 = kt * 32;
        #pragma unroll
        for (int arr = 0; arr < 2; arr++) {
            #pragma unroll
            for (int i = 0; i < 2; i++) {
                int ch = tid + i * 256;
                int row = ch >> 2, cg = ch & 3;
                uint32_t dst = smb + ((((b * 2 + arr) * 128 + row) * 40) + cg * 8) * 2;
                cp16(dst, srcs[arr] + (long)row * K + k0 + cg * 8);
            }
        }
    };

    int nk = Keff >> 5;
    issue(0, 0); CP_COMMIT;
    issue(1, 1); CP_COMMIT;

    int lrow = lane & 15, lcg = lane >> 4;

    for (int kt = 0; kt < nk; ++kt) {
        int cur = kt % 3;
        if (kt + 1 < nk) { CP_WAIT1; } else { CP_WAIT0; }
        __syncthreads();
        if (kt + 2 < nk) { issue((kt + 2) % 3, kt + 2); CP_COMMIT; }

        #pragma unroll
        for (int ks = 0; ks < 2; ++ks) {
            uint32_t af[4][4];
            #pragma unroll
            for (int mf = 0; mf < 4; mf++) {
                int row = wm * 64 + mf * 16 + lrow;
                int col = ks * 16 + lcg * 8;
                uint32_t a0 = smb + ((((cur * 2 + 0) * 128 + row) * 40) + col) * 2;
                ldsm4(af[mf][0], af[mf][1], af[mf][2], af[mf][3], a0);
            }
            uint32_t bh[2][4];
            #pragma unroll
            for (int nf2 = 0; nf2 < 2; nf2++) {
                int row = wn * 32 + nf2 * 16 + lrow;
                int col = ks * 16 + lcg * 8;
                uint32_t b0 = smb + ((((cur * 2 + 1) * 128 + row) * 40) + col) * 2;
                ldsm4(bh[nf2][0], bh[nf2][1], bh[nf2][2], bh[nf2][3], b0);
            }
            #pragma unroll
            for (int mf = 0; mf < 4; mf++)
                #pragma unroll
                for (int nf = 0; nf < 4; nf++) {
                    int g = nf >> 1, o = nf & 1;
                    mma_f16(acc[mf][nf], af[mf][0], af[mf][1], af[mf][2], af[mf][3],
                            bh[g][o], bh[g][o + 2]);
                }
        }
    }

    float* Cp = (EPI == 4) ? (C + (size_t)kz * Mq_ * (size_t)Nout) : C;

    int r = lane >> 2, c2 = (lane & 3) * 2;
    #pragma unroll
    for (int mf = 0; mf < 4; mf++) {
        #pragma unroll
        for (int nf = 0; nf < 4; nf++) {
            #pragma unroll
            for (int half2_ = 0; half2_ < 2; half2_++) {
                long row = bm + wm * 64 + mf * 16 + r + half2_ * 8;
                #pragma unroll
                for (int e = 0; e < 2; e++) {
                    int col = bn + wn * 32 + nf * 8 + c2 + e;
                    if (col < Nout) {
                        float v = acc[mf][nf][half2_ * 2 + e];
                        if (EPI == 4) {
                            if (kz == 0) v += bias[col];
                            Cp[row * (long)Nout + col] = v;
                        } else {
                            v += bias[col];
                            if (EPI == 1 || EPI == 3) {
                                if (EPI == 1)
                                    v = 0.5f * v * (1.f + erff(v * 0.70710678118654752f));
                                C16[row * N + col] = __float2half_rn(v);
                            } else {
                                Cp[row * (long)Nout + col] = v;
                            }
                        }
                    }
                }
            }
        }
    }
}

template<int EPI, bool SWAP>
__global__ __launch_bounds__(256, 1) void gemm_kernel(
    const f16* __restrict__ A,
    const f16* __restrict__ Bhi,
    const float* __restrict__ bias,
    float* __restrict__ C, f16* __restrict__ C16,
    int K, int N, int Nout)
{
    gemm_body<EPI, SWAP>(A, Bhi, bias, C, C16, K, N, Nout);
}

// fused QKV (all 1-term), blockIdx.z selects q/k/v
__global__ __launch_bounds__(256, 1) void gemm_qkv_kernel(
    const f16* __restrict__ A,
    const f16* __restrict__ whi,
    const float* __restrict__ bq, const float* __restrict__ bk, const float* __restrict__ bv,
    f16* __restrict__ q, f16* __restrict__ k, f16* __restrict__ v)
{
    int z = blockIdx.z;
    const f16* Bh = whi + (size_t)z * WSQ;
    const float* bias = (z == 0) ? bq : (z == 1) ? bk : bv;
    f16* C16 = (z == 0) ? q : (z == 1) ? k : v;
    gemm_body<3, false>(A, Bh, bias, nullptr, C16, Dq_, Dq_, Dq_);
}

// ---------------- HMMA flash attention, fp16, double-buffered, heavy-first ----------------
#define AT_STRIDE 72
#define AT_TILE (64 * AT_STRIDE)
#define ATTN_SMEM (5 * AT_TILE * 2)   // Q + 2x(K,V) = 46080

__global__ __launch_bounds__(128, 4) void attn_kernel(
    const f16* __restrict__ Qg, const f16* __restrict__ Kg, const f16* __restrict__ Vg,
    f16* __restrict__ O)
{
    extern __shared__ f16 asm_[];
    uint32_t smb = s2u(asm_);
    uint32_t sQ = smb;

    int t = threadIdx.x, warp = t >> 5, lane = t & 31;
    int qt = (int)gridDim.x - 1 - (int)blockIdx.x;   // LPT: heavy first
    int q0 = qt * 64, h = blockIdx.y, b = blockIdx.z;

    long rowbase = (long)(b * Sq_ + q0) * Dq_ + h * DHq_;

    auto issue_kv = [&](int buf, int jt) {
        uint32_t sK = smb + (1 + buf * 2) * AT_TILE * 2;
        uint32_t sV = sK + AT_TILE * 2;
        long kbase = (long)(b * Sq_ + jt * 64) * Dq_ + h * DHq_;
        #pragma unroll
        for (int i = 0; i < 4; i++) {
            int idx = t + i * 128;
            int row = idx >> 3, ch = idx & 7;
            uint32_t doff = (uint32_t)(row * AT_STRIDE + ch * 8) * 2;
            long goff = kbase + (long)row * Dq_ + ch * 8;
            cp16(sK + doff, Kg + goff);
            cp16(sV + doff, Vg + goff);
        }
    };

    #pragma unroll
    for (int i = 0; i < 4; i++) {
        int idx = t + i * 128;
        int row = idx >> 3, ch = idx & 7;
        uint32_t doff = (uint32_t)(row * AT_STRIDE + ch * 8) * 2;
        cp16(sQ + doff, Qg + rowbase + (long)row * Dq_ + ch * 8);
    }
    issue_kv(0, 0);
    CP_COMMIT;

    float m[2] = { -1e30f, -1e30f }, l[2] = { 0.f, 0.f };
    float oacc[8][4];
    #pragma unroll
    for (int i = 0; i < 8; i++)
        #pragma unroll
        for (int j = 0; j < 4; j++) oacc[i][j] = 0.f;

    int lrow = lane & 15, lcg = lane >> 4;
    int ntiles = q0 / 64 + 1;

    for (int it = 0; it < ntiles; ++it) {
        if (it + 1 < ntiles) { issue_kv((it + 1) & 1, it + 1); CP_COMMIT; CP_WAIT1; }
        else                 { CP_WAIT0; }
        __syncthreads();

        uint32_t sK = smb + (1 + (it & 1) * 2) * AT_TILE * 2;
        uint32_t sV = sK + AT_TILE * 2;
        int j0 = it * 64;

        float sacc[8][4];
        #pragma unroll
        for (int i = 0; i < 8; i++)
            #pragma unroll
            for (int j = 0; j < 4; j++) sacc[i][j] = 0.f;

        #pragma unroll
        for (int ks = 0; ks < 4; ++ks) {
            int acol = ks * 16 + lcg * 8;
            uint32_t qf[4];
            uint32_t qaddr = (uint32_t)((warp * 16 + lrow) * AT_STRIDE + acol) * 2;
            ldsm4(qf[0], qf[1], qf[2], qf[3], sQ + qaddr);
            uint32_t kf[4][4];
            #pragma unroll
            for (int kg = 0; kg < 4; ++kg) {
                uint32_t kaddr = (uint32_t)((kg * 16 + lrow) * AT_STRIDE + acol) * 2;
                ldsm4(kf[kg][0], kf[kg][1], kf[kg][2], kf[kg][3], sK + kaddr);
            }
            #pragma unroll
            for (int kg = 0; kg < 4; ++kg)
                #pragma unroll
                for (int o = 0; o < 2; ++o)
                    mma_f16(sacc[kg * 2 + o], qf[0], qf[1], qf[2], qf[3], kf[kg][o], kf[kg][o + 2]);
        }

        int r0loc = warp * 16 + (lane >> 2);
        bool diag = (j0 == q0);
        float mx[2] = { -1e30f, -1e30f };
        #pragma unroll
        for (int nf = 0; nf < 8; nf++) {
            #pragma unroll
            for (int i = 0; i < 4; i++) {
                float v = sacc[nf][i] * 0.125f;
                if (diag) {
                    int col = nf * 8 + (lane & 3) * 2 + (i & 1);
                    int row = r0loc + ((i >> 1) ? 8 : 0);
                    if (col > row) v = -1e30f;
                }
                sacc[nf][i] = v;
                mx[i >> 1] = fmaxf(mx[i >> 1], v);
            }
        }
        #pragma unroll
        for (int o = 1; o < 4; o <<= 1) {
            mx[0] = fmaxf(mx[0], __shfl_xor_sync(0xffffffffu, mx[0], o));
            mx[1] = fmaxf(mx[1], __shfl_xor_sync(0xffffffffu, mx[1], o));
        }
        float fac[2], sum[2] = { 0.f, 0.f };
        #pragma unroll
        for (int j = 0; j < 2; j++) {
            float mnew = fmaxf(m[j], mx[j]);
            fac[j] = __expf(m[j] - mnew);
            m[j] = mnew;
        }
        #pragma unroll
        for (int nf = 0; nf < 8; nf++) {
            #pragma unroll
            for (int i = 0; i < 4; i++) {
                float p = __expf(sacc[nf][i] - m[i >> 1]);
                sacc[nf][i] = p;
                sum[i >> 1] += p;
            }
        }
        #pragma unroll
        for (int o = 1; o < 4; o <<= 1) {
            sum[0] += __shfl_xor_sync(0xffffffffu, sum[0], o);
            sum[1] += __shfl_xor_sync(0xffffffffu, sum[1], o);
        }
        #pragma unroll
        for (int j = 0; j < 2; j++) l[j] = l[j] * fac[j] + sum[j];
        #pragma unroll
        for (int nf = 0; nf < 8; nf++) {
            oacc[nf][0] *= fac[0]; oacc[nf][1] *= fac[0];
            oacc[nf][2] *= fac[1]; oacc[nf][3] *= fac[1];
        }

        #pragma unroll
        for (int t2 = 0; t2 < 4; ++t2) {
            float* p0 = sacc[2 * t2];
            float* p1 = sacc[2 * t2 + 1];
            uint32_t pa[4];
            pa[0] = packh2(p0[0], p0[1]);
            pa[1] = packh2(p0[2], p0[3]);
            pa[2] = packh2(p1[0], p1[1]);
            pa[3] = packh2(p1[2], p1[3]);

            uint32_t vf[4][4];
            #pragma unroll
            for (int nd = 0; nd < 4; ++nd) {
                uint32_t vrow = (uint32_t)(t2 * 16 + ((lane >> 4) << 3) + (lane & 7));
                uint32_t vcol = (uint32_t)(nd * 16 + (((lane >> 3) & 1) << 3));
                uint32_t vaddr = (vrow * AT_STRIDE + vcol) * 2;
                ldsm4t(vf[nd][0], vf[nd][1], vf[nd][2], vf[nd][3], sV + vaddr);
            }
            #pragma unroll
            for (int nd = 0; nd < 4; ++nd)
                #pragma unroll
                for (int o = 0; o < 2; ++o)
                    mma_f16(oacc[nd * 2 + o], pa[0], pa[1], pa[2], pa[3], vf[nd][o], vf[nd][o + 2]);
        }
        __syncthreads();
    }

    float inv0 = 1.f / l[0], inv1 = 1.f / l[1];
    long row0 = (long)(b * Sq_ + q0 + warp * 16 + (lane >> 2));
    long row1 = row0 + 8;
    #pragma unroll
    for (int nf = 0; nf < 8; nf++) {
        int col = h * DHq_ + nf * 8 + (lane & 3) * 2;
        *(__half2*)&O[row0 * Dq_ + col] = __floats2half2_rn(oacc[nf][0] * inv0, oacc[nf][1] * inv0);
        *(__half2*)&O[row1 * Dq_ + col] = __floats2half2_rn(oacc[nf][2] * inv1, oacc[nf][3] * inv1);
    }
}

// ---------------- launcher ----------------
extern "C" void kernel_launch(void* const* d_in, const int* in_sizes, int n_in,
                              void* d_out, int out_size) {
    const int*   x    = (const int*)  d_in[0];
    const float* tok  = (const float*)d_in[1];
    const float* pos  = (const float*)d_in[2];
    const float* Wq   = (const float*)d_in[3];
    const float* bq   = (const float*)d_in[4];
    const float* Wk   = (const float*)d_in[5];
    const float* bk   = (const float*)d_in[6];
    const float* Wv   = (const float*)d_in[7];
    const float* bv   = (const float*)d_in[8];
    const float* Wo   = (const float*)d_in[9];
    const float* bo   = (const float*)d_in[10];
    const float* ln1w = (const float*)d_in[11];
    const float* ln1b = (const float*)d_in[12];
    const float* ln2w = (const float*)d_in[13];
    const float* ln2b = (const float*)d_in[14];
    const float* W1   = (const float*)d_in[15];
    const float* b1   = (const float*)d_in[16];
    const float* W2   = (const float*)d_in[17];
    const float* b2   = (const float*)d_in[18];
    const float* lnfw = (const float*)d_in[19];
    const float* lnfb = (const float*)d_in[20];
    const float* Wout = (const float*)d_in[21];
    const float* bout = (const float*)d_in[22];
    float* out = (float*)d_out;

    float *h, *p;
    f16 *a, *q, *k, *v, *o, *f, *whi;
    cudaGetSymbolAddress((void**)&h, g_h);
    cudaGetSymbolAddress((void**)&p, g_p);
    cudaGetSymbolAddress((void**)&a, g_a);
    cudaGetSymbolAddress((void**)&q, g_q);
    cudaGetSymbolAddress((void**)&k, g_k);
    cudaGetSymbolAddress((void**)&v, g_v);
    cudaGetSymbolAddress((void**)&o, g_o);
    cudaGetSymbolAddress((void**)&f, g_f);
    cudaGetSymbolAddress((void**)&whi, g_whi);
    float* p0 = p;
    float* p1 = p + (size_t)Mq_ * Dq_;
    float* p2 = p + 2 * (size_t)Mq_ * Dq_;

    cudaFuncSetAttribute((const void*)gemm_kernel<0,true>,  cudaFuncAttributeMaxDynamicSharedMemorySize, GEMM_SMEM);
    cudaFuncSetAttribute((const void*)gemm_kernel<1,false>, cudaFuncAttributeMaxDynamicSharedMemorySize, GEMM_SMEM);
    cudaFuncSetAttribute((const void*)gemm_kernel<4,false>, cudaFuncAttributeMaxDynamicSharedMemorySize, GEMM_SMEM);
    cudaFuncSetAttribute((const void*)gemm_qkv_kernel, cudaFuncAttributeMaxDynamicSharedMemorySize, GEMM_SMEM);
    cudaFuncSetAttribute((const void*)attn_kernel, cudaFuncAttributeMaxDynamicSharedMemorySize, ATTN_SMEM);

    // ---- weight prep (batched, fp16 1-term) ----
    dim3 tb(32, 8);
    tsplit_sq_kernel<<<dim3(24, 24, 48), tb>>>(Wq, Wk, Wv, Wo, whi);
    tsplit_w1_kernel<<<dim3(Hq_ / 32, 24, 12), tb>>>(W1, whi);
    tsplit_w2_kernel<<<dim3(24, Hq_ / 32, 12), tb>>>(W2, whi);
    tsplit_out_kernel<<<dim3(VPAD_ / 32, 24), tb>>>(Wout, whi);

    embed_kernel<<<Mq_, 256>>>(x, tok, pos, h);

    dim3 gQKV(Dq_ / 128, Mq_ / 128, 3);  // 6 x 32 x 3 = 576 blocks
    dim3 gDs3(Dq_ / 128, Mq_ / 128, 3);  // split-K3
    dim3 gH(Hq_ / 128, Mq_ / 128);
    dim3 gVsw(Mq_ / 128, VPAD_ / 128);
    dim3 gAtt(Sq_ / 64, NHq_, Bq_);
    const int LNG = Mq_ / 8;

    for (int i = 0; i < Lq_; ++i) {
        size_t off = (size_t)i * LWBLK;
        if (i == 0)
            ln_warp_kernel<false,false><<<LNG, 256>>>(h, nullptr, nullptr, nullptr, ln1w, ln1b, a);
        else
            ln_warp_kernel<true,true><<<LNG, 256>>>(h, p0, p1, p2, ln1w + i * Dq_, ln1b + i * Dq_, a);

        gemm_qkv_kernel<<<gQKV, 256, GEMM_SMEM>>>(a, whi + off,
            bq + i * Dq_, bk + i * Dq_, bv + i * Dq_, q, k, v);
        attn_kernel<<<gAtt, 128, ATTN_SMEM>>>(q, k, v, o);

        gemm_kernel<4,false><<<gDs3, 256, GEMM_SMEM>>>(o, whi + off + 3 * WSQ,
            bo + i * Dq_, p, nullptr, Dq_, Dq_, Dq_);

        ln_warp_kernel<true,true><<<LNG, 256>>>(h, p0, p1, p2, ln2w + i * Dq_, ln2b + i * Dq_, a);

        gemm_kernel<1,false><<<gH, 256, GEMM_SMEM>>>(a, whi + off + 4 * WSQ,
            b1 + i * Hq_, nullptr, f, Dq_, Hq_, Hq_);

        gemm_kernel<4,false><<<gDs3, 256, GEMM_SMEM>>>(f, whi + off + 4 * WSQ + WSH,
            b2 + i * Dq_, p, nullptr, Hq_, Dq_, Dq_);
    }

    ln_warp_kernel<true,false><<<LNG, 256>>>(h, p0, p1, p2, lnfw, lnfb, a);
    gemm_kernel<0,true><<<gVsw, 256, GEMM_SMEM>>>(a, whi + WOUT_OFF,
        bout, out, nullptr, Dq_, VPAD_, Vq_);
}

// round 14
// speedup vs baseline: 1.3988x; 1.0992x over previous
#include <cuda_runtime.h>
#include <cuda_fp16.h>
#include <math.h>
#include <stdint.h>

// ---------------- problem constants ----------------
#define Bq_ 4
#define Sq_ 1024
#define Vq_ 50257
#define VPAD_ 50304
#define Dq_ 768
#define Hq_ 3072
#define NHq_ 12
#define DHq_ 64
#define Lq_ 12
#define Mq_ (Bq_*Sq_)   // 4096 rows

typedef __half f16;

#define WSQ (768UL*768UL)
#define WSH (768UL*3072UL)
#define LWBLK (4UL*WSQ + 2UL*WSH)
#define WOUT_OFF (LWBLK*12UL)
#define WTOT (WOUT_OFF + (size_t)VPAD_*Dq_)

// ---------------- scratch (device globals; no allocs allowed) ----------------
__device__ float g_h[Mq_*Dq_];
__device__ float g_p[3UL*Mq_*Dq_];          // split-K3 partial planes
__device__ f16 g_a[Mq_*Dq_];
__device__ f16 g_q[Mq_*Dq_];
__device__ f16 g_k[Mq_*Dq_];
__device__ f16 g_v[Mq_*Dq_];
__device__ f16 g_o[Mq_*Dq_];
__device__ f16 g_f[Mq_*Hq_];
__device__ f16 g_whi[WTOT];

// ---------------- helpers ----------------
__device__ __forceinline__ uint32_t s2u(const void* p) {
    return (uint32_t)__cvta_generic_to_shared(p);
}
__device__ __forceinline__ void cp16(uint32_t d, const void* s) {
    asm volatile("cp.async.cg.shared.global [%0], [%1], 16;\n" :: "r"(d), "l"(s) : "memory");
}
#define CP_COMMIT asm volatile("cp.async.commit_group;\n" ::: "memory")
#define CP_WAIT1  asm volatile("cp.async.wait_group 1;\n" ::: "memory")
#define CP_WAIT0  asm volatile("cp.async.wait_group 0;\n" ::: "memory")

__device__ __forceinline__ void ldsm4(uint32_t &r0, uint32_t &r1, uint32_t &r2, uint32_t &r3,
                                      uint32_t addr) {
    asm volatile("ldmatrix.sync.aligned.m8n8.x4.shared.b16 {%0,%1,%2,%3}, [%4];\n"
        : "=r"(r0), "=r"(r1), "=r"(r2), "=r"(r3) : "r"(addr));
}
__device__ __forceinline__ void ldsm4t(uint32_t &r0, uint32_t &r1, uint32_t &r2, uint32_t &r3,
                                       uint32_t addr) {
    asm volatile("ldmatrix.sync.aligned.m8n8.x4.trans.shared.b16 {%0,%1,%2,%3}, [%4];\n"
        : "=r"(r0), "=r"(r1), "=r"(r2), "=r"(r3) : "r"(addr));
}
__device__ __forceinline__ void mma_f16(float* c, uint32_t a0, uint32_t a1, uint32_t a2, uint32_t a3,
                                        uint32_t b0, uint32_t b1) {
    asm volatile("mma.sync.aligned.m16n8k16.row.col.f32.f16.f16.f32 "
        "{%0,%1,%2,%3},{%4,%5,%6,%7},{%8,%9},{%0,%1,%2,%3};\n"
        : "+f"(c[0]), "+f"(c[1]), "+f"(c[2]), "+f"(c[3])
        : "r"(a0), "r"(a1), "r"(a2), "r"(a3), "r"(b0), "r"(b1));
}
__device__ __forceinline__ uint32_t packh2(float a, float b) {
    __half2 t = __floats2half2_rn(a, b);
    return *(uint32_t*)&t;
}

// ---------------- weight transpose (fp16, 1-term), batched ----------------
__device__ __forceinline__ void tsplit_body(const float* __restrict__ W, f16* __restrict__ hi,
                                            int K, int Nsrc) {
    __shared__ float tile[32][33];
    int k0 = blockIdx.y * 32, n0 = blockIdx.x * 32;
    int tx = threadIdx.x, ty = threadIdx.y;
    #pragma unroll
    for (int i = 0; i < 4; i++) {
        int k = k0 + ty + i * 8, n = n0 + tx;
        tile[ty + i * 8][tx] = (n < Nsrc) ? W[(long)k * Nsrc + n] : 0.f;
    }
    __syncthreads();
    #pragma unroll
    for (int i = 0; i < 4; i++) {
        int n = n0 + ty + i * 8, k = k0 + tx;
        hi[(long)n * K + k] = __float2half_rn(tile[tx][ty + i * 8]);
    }
}

__global__ void tsplit_sq_kernel(const float* __restrict__ Wq, const float* __restrict__ Wk,
                                 const float* __restrict__ Wv, const float* __restrict__ Wo,
                                 f16* __restrict__ hi) {
    int z = blockIdx.z, layer = z >> 2, which = z & 3;
    const float* W = (which == 0 ? Wq : which == 1 ? Wk : which == 2 ? Wv : Wo) + (size_t)layer * WSQ;
    size_t off = (size_t)layer * LWBLK + (size_t)which * WSQ;
    tsplit_body(W, hi + off, 768, 768);
}
__global__ void tsplit_w1_kernel(const float* __restrict__ W1, f16* __restrict__ hi) {
    int layer = blockIdx.z;
    size_t off = (size_t)layer * LWBLK + 4 * WSQ;
    tsplit_body(W1 + (size_t)layer * WSH, hi + off, 768, Hq_);
}
__global__ void tsplit_w2_kernel(const float* __restrict__ W2, f16* __restrict__ hi) {
    int layer = blockIdx.z;
    size_t off = (size_t)layer * LWBLK + 4 * WSQ + WSH;
    tsplit_body(W2 + (size_t)layer * WSH, hi + off, Hq_, 768);
}
__global__ void tsplit_out_kernel(const float* __restrict__ W, f16* __restrict__ hi) {
    tsplit_body(W, hi + WOUT_OFF, 768, Vq_);
}

// ---------------- embedding ----------------
__global__ void embed_kernel(const int* __restrict__ x,
                             const float* __restrict__ tok,
                             const float* __restrict__ pos,
                             float* __restrict__ h) {
    int row = blockIdx.x;
    int s = row & (Sq_ - 1);
    int tid = x[row];
    const float* tp = tok + (long)tid * Dq_;
    const float* pp = pos + (long)s * Dq_;
    float* hp = h + (long)row * Dq_;
    for (int d = threadIdx.x; d < Dq_; d += 256)
        hp[d] = tp[d] + pp[d];
}

// ---------------- warp-per-row layernorm (+ optional partial-plane sum) ----------------
template<bool SUM, bool WRITEH>
__global__ __launch_bounds__(256) void ln_warp_kernel(
    float* __restrict__ H,
    const float* __restrict__ P0, const float* __restrict__ P1, const float* __restrict__ P2,
    const float* __restrict__ w, const float* __restrict__ bb,
    f16* __restrict__ Y)
{
    int warp = threadIdx.x >> 5, lane = threadIdx.x & 31;
    long base = ((long)blockIdx.x * 8 + warp) * Dq_;

    float4 v[6];
    #pragma unroll
    for (int j = 0; j < 6; j++) {
        int idx = (lane + j * 32) * 4;
        float4 hv = *(const float4*)&H[base + idx];
        if (SUM) {
            float4 a0 = *(const float4*)&P0[base + idx];
            float4 a1 = *(const float4*)&P1[base + idx];
            float4 a2 = *(const float4*)&P2[base + idx];
            hv.x += a0.x + a1.x + a2.x;
            hv.y += a0.y + a1.y + a2.y;
            hv.z += a0.z + a1.z + a2.z;
            hv.w += a0.w + a1.w + a2.w;
            if (WRITEH) *(float4*)&H[base + idx] = hv;
        }
        v[j] = hv;
    }

    float s = 0.f;
    #pragma unroll
    for (int j = 0; j < 6; j++) s += v[j].x + v[j].y + v[j].z + v[j].w;
    #pragma unroll
    for (int o = 16; o > 0; o >>= 1) s += __shfl_xor_sync(0xffffffffu, s, o);
    float mean = s * (1.0f / Dq_);

    float q = 0.f;
    #pragma unroll
    for (int j = 0; j < 6; j++) {
        v[j].x -= mean; v[j].y -= mean; v[j].z -= mean; v[j].w -= mean;
        q += v[j].x * v[j].x + v[j].y * v[j].y + v[j].z * v[j].z + v[j].w * v[j].w;
    }
    #pragma unroll
    for (int o = 16; o > 0; o >>= 1) q += __shfl_xor_sync(0xffffffffu, q, o);
    float inv = rsqrtf(q * (1.0f / Dq_) + 1e-5f);

    #pragma unroll
    for (int j = 0; j < 6; j++) {
        int idx = (lane + j * 32) * 4;
        float4 wv = *(const float4*)&w[idx];
        float4 bv = *(const float4*)&bb[idx];
        uint2 outp;
        outp.x = packh2(v[j].x * inv * wv.x + bv.x, v[j].y * inv * wv.y + bv.y);
        outp.y = packh2(v[j].z * inv * wv.z + bv.z, v[j].w * inv * wv.w + bv.w);
        *(uint2*)&Y[base + idx] = outp;
    }
}

// ---------------- fp16 HMMA GEMM, 1-term, 3-stage pipeline, 2 CTAs/SM ----------------
// C = A[MxK](f16) * Bh^T + bias
// EPI: 0 = fp32 C+bias; 1 = GELU -> f16; 3 = f16 out; 4 = split-K3 fp32 partial plane
#define GEMM_SMEM (3 * 2 * 128 * 40 * 2)   // 61440

template<int EPI, bool SWAP>
__device__ __forceinline__ void gemm_body(
    const f16* __restrict__ A,
    const f16* __restrict__ Bhi,
    const float* __restrict__ bias,
    float* __restrict__ C, f16* __restrict__ C16,
    int K, int N, int Nout)
{
    extern __shared__ f16 sm[];    // [3 buf][2 arr][128][40]
    uint32_t smb = s2u(sm);
    int tid = threadIdx.x;
    int bm = (SWAP ? blockIdx.x : blockIdx.y) * 128;
    int bn = (SWAP ? blockIdx.y : blockIdx.x) * 128;
    int warp = tid >> 5, lane = tid & 31;
    int wm = warp >> 2, wn = warp & 3;

    int kz = (EPI == 4) ? blockIdx.z : 0;
    int Keff = (EPI == 4) ? (K / 3) : K;
    long koff = (long)kz * Keff;

    float acc[4][4][4];
    #pragma unroll
    for (int i = 0; i < 4; i++)
        #pragma unroll
        for (int j = 0; j < 4; j++)
            #pragma unroll
            for (int k = 0; k < 4; k++) acc[i][j][k] = 0.f;

    const f16* srcs[2] = { A + (long)bm * K + koff, Bhi + (long)bn * K + koff };

    auto issue = [&](int b, int kt) {
        int k0 = kt * 32;
        #pragma unroll
        for (int arr = 0; arr < 2; arr++) {
            #pragma unroll
            for (int i = 0; i < 2; i++) {
                int ch = tid + i * 256;
                int row = ch >> 2, cg = ch & 3;
                uint32_t dst = smb + ((((b * 2 + arr) * 128 + row) * 40) + cg * 8) * 2;
                cp16(dst, srcs[arr] + (long)row * K + k0 + cg * 8);
            }
        }
    };

    int nk = Keff >> 5;
    issue(0, 0); CP_COMMIT;
    issue(1, 1); CP_COMMIT;

    int lrow = lane & 15, lcg = lane >> 4;

    for (int kt = 0; kt < nk; ++kt) {
        int cur = kt % 3;
        if (kt + 1 < nk) { CP_WAIT1; } else { CP_WAIT0; }
        __syncthreads();
        if (kt + 2 < nk) { issue((kt + 2) % 3, kt + 2); CP_COMMIT; }

        #pragma unroll
        for (int ks = 0; ks < 2; ++ks) {
            uint32_t af[4][4];
            #pragma unroll
            for (int mf = 0; mf < 4; mf++) {
                int row = wm * 64 + mf * 16 + lrow;
                int col = ks * 16 + lcg * 8;
                uint32_t a0 = smb + ((((cur * 2 + 0) * 128 + row) * 40) + col) * 2;
                ldsm4(af[mf][0], af[mf][1], af[mf][2], af[mf][3], a0);
            }
            uint32_t bh[2][4];
            #pragma unroll
            for (int nf2 = 0; nf2 < 2; nf2++) {
                int row = wn * 32 + nf2 * 16 + lrow;
                int col = ks * 16 + lcg * 8;
                uint32_t b0 = smb + ((((cur * 2 + 1) * 128 + row) * 40) + col) * 2;
                ldsm4(bh[nf2][0], bh[nf2][1], bh[nf2][2], bh[nf2][3], b0);
            }
            #pragma unroll
            for (int mf = 0; mf < 4; mf++)
                #pragma unroll
                for (int nf = 0; nf < 4; nf++) {
                    int g = nf >> 1, o = nf & 1;
                    mma_f16(acc[mf][nf], af[mf][0], af[mf][1], af[mf][2], af[mf][3],
                            bh[g][o], bh[g][o + 2]);
                }
        }
    }

    float* Cp = (EPI == 4) ? (C + (size_t)kz * Mq_ * (size_t)Nout) : C;

    int r = lane >> 2, c2 = (lane & 3) * 2;
    #pragma unroll
    for (int mf = 0; mf < 4; mf++) {
        #pragma unroll
        for (int nf = 0; nf < 4; nf++) {
            #pragma unroll
            for (int half2_ = 0; half2_ < 2; half2_++) {
                long row = bm + wm * 64 + mf * 16 + r + half2_ * 8;
                #pragma unroll
                for (int e = 0; e < 2; e++) {
                    int col = bn + wn * 32 + nf * 8 + c2 + e;
                    if (col < Nout) {
                        float v = acc[mf][nf][half2_ * 2 + e];
                        if (EPI == 4) {
                            if (kz == 0) v += bias[col];
                            Cp[row * (long)Nout + col] = v;
                        } else {
                            v += bias[col];
                            if (EPI == 1 || EPI == 3) {
                                if (EPI == 1)
                                    v = 0.5f * v * (1.f + erff(v * 0.70710678118654752f));
                                C16[row * N + col] = __float2half_rn(v);
                            } else {
                                Cp[row * (long)Nout + col] = v;
                            }
                        }
                    }
                }
            }
        }
    }
}

template<int EPI, bool SWAP>
__global__ __launch_bounds__(256, 2) void gemm_kernel(
    const f16* __restrict__ A,
    const f16* __restrict__ Bhi,
    const float* __restrict__ bias,
    float* __restrict__ C, f16* __restrict__ C16,
    int K, int N, int Nout)
{
    gemm_body<EPI, SWAP>(A, Bhi, bias, C, C16, K, N, Nout);
}

// fused QKV (all 1-term), blockIdx.z selects q/k/v
__global__ __launch_bounds__(256, 2) void gemm_qkv_kernel(
    const f16* __restrict__ A,
    const f16* __restrict__ whi,
    const float* __restrict__ bq, const float* __restrict__ bk, const float* __restrict__ bv,
    f16* __restrict__ q, f16* __restrict__ k, f16* __restrict__ v)
{
    int z = blockIdx.z;
    const f16* Bh = whi + (size_t)z * WSQ;
    const float* bias = (z == 0) ? bq : (z == 1) ? bk : bv;
    f16* C16 = (z == 0) ? q : (z == 1) ? k : v;
    gemm_body<3, false>(A, Bh, bias, nullptr, C16, Dq_, Dq_, Dq_);
}

// ---------------- HMMA flash attention, fp16, double-buffered, heavy-first ----------------
#define AT_STRIDE 72
#define AT_TILE (64 * AT_STRIDE)
#define ATTN_SMEM (5 * AT_TILE * 2)   // Q + 2x(K,V) = 46080

__global__ __launch_bounds__(128, 4) void attn_kernel(
    const f16* __restrict__ Qg, const f16* __restrict__ Kg, const f16* __restrict__ Vg,
    f16* __restrict__ O)
{
    extern __shared__ f16 asm_[];
    uint32_t smb = s2u(asm_);
    uint32_t sQ = smb;

    int t = threadIdx.x, warp = t >> 5, lane = t & 31;
    int qt = (int)gridDim.x - 1 - (int)blockIdx.x;   // LPT: heavy first
    int q0 = qt * 64, h = blockIdx.y, b = blockIdx.z;

    long rowbase = (long)(b * Sq_ + q0) * Dq_ + h * DHq_;

    auto issue_kv = [&](int buf, int jt) {
        uint32_t sK = smb + (1 + buf * 2) * AT_TILE * 2;
        uint32_t sV = sK + AT_TILE * 2;
        long kbase = (long)(b * Sq_ + jt * 64) * Dq_ + h * DHq_;
        #pragma unroll
        for (int i = 0; i < 4; i++) {
            int idx = t + i * 128;
            int row = idx >> 3, ch = idx & 7;
            uint32_t doff = (uint32_t)(row * AT_STRIDE + ch * 8) * 2;
            long goff = kbase + (long)row * Dq_ + ch * 8;
            cp16(sK + doff, Kg + goff);
            cp16(sV + doff, Vg + goff);
        }
    };

    #pragma unroll
    for (int i = 0; i < 4; i++) {
        int idx = t + i * 128;
        int row = idx >> 3, ch = idx & 7;
        uint32_t doff = (uint32_t)(row * AT_STRIDE + ch * 8) * 2;
        cp16(sQ + doff, Qg + rowbase + (long)row * Dq_ + ch * 8);
    }
    issue_kv(0, 0);
    CP_COMMIT;

    float m[2] = { -1e30f, -1e30f }, l[2] = { 0.f, 0.f };
    float oacc[8][4];
    #pragma unroll
    for (int i = 0; i < 8; i++)
        #pragma unroll
        for (int j = 0; j < 4; j++) oacc[i][j] = 0.f;

    int lrow = lane & 15, lcg = lane >> 4;
    int ntiles = q0 / 64 + 1;

    for (int it = 0; it < ntiles; ++it) {
        if (it + 1 < ntiles) { issue_kv((it + 1) & 1, it + 1); CP_COMMIT; CP_WAIT1; }
        else                 { CP_WAIT0; }
        __syncthreads();

        uint32_t sK = smb + (1 + (it & 1) * 2) * AT_TILE * 2;
        uint32_t sV = sK + AT_TILE * 2;
        int j0 = it * 64;

        float sacc[8][4];
        #pragma unroll
        for (int i = 0; i < 8; i++)
            #pragma unroll
            for (int j = 0; j < 4; j++) sacc[i][j] = 0.f;

        #pragma unroll
        for (int ks = 0; ks < 4; ++ks) {
            int acol = ks * 16 + lcg * 8;
            uint32_t qf[4];
            uint32_t qaddr = (uint32_t)((warp * 16 + lrow) * AT_STRIDE + acol) * 2;
            ldsm4(qf[0], qf[1], qf[2], qf[3], sQ + qaddr);
            uint32_t kf[4][4];
            #pragma unroll
            for (int kg = 0; kg < 4; ++kg) {
                uint32_t kaddr = (uint32_t)((kg * 16 + lrow) * AT_STRIDE + acol) * 2;
                ldsm4(kf[kg][0], kf[kg][1], kf[kg][2], kf[kg][3], sK + kaddr);
            }
            #pragma unroll
            for (int kg = 0; kg < 4; ++kg)
                #pragma unroll
                for (int o = 0; o < 2; ++o)
                    mma_f16(sacc[kg * 2 + o], qf[0], qf[1], qf[2], qf[3], kf[kg][o], kf[kg][o + 2]);
        }

        int r0loc = warp * 16 + (lane >> 2);
        bool diag = (j0 == q0);
        float mx[2] = { -1e30f, -1e30f };
        #pragma unroll
        for (int nf = 0; nf < 8; nf++) {
            #pragma unroll
            for (int i = 0; i < 4; i++) {
                float v = sacc[nf][i] * 0.125f;
                if (diag) {
                    int col = nf * 8 + (lane & 3) * 2 + (i & 1);
                    int row = r0loc + ((i >> 1) ? 8 : 0);
                    if (col > row) v = -1e30f;
                }
                sacc[nf][i] = v;
                mx[i >> 1] = fmaxf(mx[i >> 1], v);
            }
        }
        #pragma unroll
        for (int o = 1; o < 4; o <<= 1) {
            mx[0] = fmaxf(mx[0], __shfl_xor_sync(0xffffffffu, mx[0], o));
            mx[1] = fmaxf(mx[1], __shfl_xor_sync(0xffffffffu, mx[1], o));
        }
        float fac[2], sum[2] = { 0.f, 0.f };
        #pragma unroll
        for (int j = 0; j < 2; j++) {
            float mnew = fmaxf(m[j], mx[j]);
            fac[j] = __expf(m[j] - mnew);
            m[j] = mnew;
        }
        #pragma unroll
        for (int nf = 0; nf < 8; nf++) {
            #pragma unroll
            for (int i = 0; i < 4; i++) {
                float p = __expf(sacc[nf][i] - m[i >> 1]);
                sacc[nf][i] = p;
                sum[i >> 1] += p;
            }
        }
        #pragma unroll
        for (int o = 1; o < 4; o <<= 1) {
            sum[0] += __shfl_xor_sync(0xffffffffu, sum[0], o);
            sum[1] += __shfl_xor_sync(0xffffffffu, sum[1], o);
        }
        #pragma unroll
        for (int j = 0; j < 2; j++) l[j] = l[j] * fac[j] + sum[j];
        #pragma unroll
        for (int nf = 0; nf < 8; nf++) {
            oacc[nf][0] *= fac[0]; oacc[nf][1] *= fac[0];
            oacc[nf][2] *= fac[1]; oacc[nf][3] *= fac[1];
        }

        #pragma unroll
        for (int t2 = 0; t2 < 4; ++t2) {
            float* p0 = sacc[2 * t2];
            float* p1 = sacc[2 * t2 + 1];
            uint32_t pa[4];
            pa[0] = packh2(p0[0], p0[1]);
            pa[1] = packh2(p0[2], p0[3]);
            pa[2] = packh2(p1[0], p1[1]);
            pa[3] = packh2(p1[2], p1[3]);

            uint32_t vf[4][4];
            #pragma unroll
            for (int nd = 0; nd < 4; ++nd) {
                uint32_t vrow = (uint32_t)(t2 * 16 + ((lane >> 4) << 3) + (lane & 7));
                uint32_t vcol = (uint32_t)(nd * 16 + (((lane >> 3) & 1) << 3));
                uint32_t vaddr = (vrow * AT_STRIDE + vcol) * 2;
                ldsm4t(vf[nd][0], vf[nd][1], vf[nd][2], vf[nd][3], sV + vaddr);
            }
            #pragma unroll
            for (int nd = 0; nd < 4; ++nd)
                #pragma unroll
                for (int o = 0; o < 2; ++o)
                    mma_f16(oacc[nd * 2 + o], pa[0], pa[1], pa[2], pa[3], vf[nd][o], vf[nd][o + 2]);
        }
        __syncthreads();
    }

    float inv0 = 1.f / l[0], inv1 = 1.f / l[1];
    long row0 = (long)(b * Sq_ + q0 + warp * 16 + (lane >> 2));
    long row1 = row0 + 8;
    #pragma unroll
    for (int nf = 0; nf < 8; nf++) {
        int col = h * DHq_ + nf * 8 + (lane & 3) * 2;
        *(__half2*)&O[row0 * Dq_ + col] = __floats2half2_rn(oacc[nf][0] * inv0, oacc[nf][1] * inv0);
        *(__half2*)&O[row1 * Dq_ + col] = __floats2half2_rn(oacc[nf][2] * inv1, oacc[nf][3] * inv1);
    }
}

// ---------------- launcher ----------------
extern "C" void kernel_launch(void* const* d_in, const int* in_sizes, int n_in,
                              void* d_out, int out_size) {
    const int*   x    = (const int*)  d_in[0];
    const float* tok  = (const float*)d_in[1];
    const float* pos  = (const float*)d_in[2];
    const float* Wq   = (const float*)d_in[3];
    const float* bq   = (const float*)d_in[4];
    const float* Wk   = (const float*)d_in[5];
    const float* bk   = (const float*)d_in[6];
    const float* Wv   = (const float*)d_in[7];
    const float* bv   = (const float*)d_in[8];
    const float* Wo   = (const float*)d_in[9];
    const float* bo   = (const float*)d_in[10];
    const float* ln1w = (const float*)d_in[11];
    const float* ln1b = (const float*)d_in[12];
    const float* ln2w = (const float*)d_in[13];
    const float* ln2b = (const float*)d_in[14];
    const float* W1   = (const float*)d_in[15];
    const float* b1   = (const float*)d_in[16];
    const float* W2   = (const float*)d_in[17];
    const float* b2   = (const float*)d_in[18];
    const float* lnfw = (const float*)d_in[19];
    const float* lnfb = (const float*)d_in[20];
    const float* Wout = (const float*)d_in[21];
    const float* bout = (const float*)d_in[22];
    float* out = (float*)d_out;

    float *h, *p;
    f16 *a, *q, *k, *v, *o, *f, *whi;
    cudaGetSymbolAddress((void**)&h, g_h);
    cudaGetSymbolAddress((void**)&p, g_p);
    cudaGetSymbolAddress((void**)&a, g_a);
    cudaGetSymbolAddress((void**)&q, g_q);
    cudaGetSymbolAddress((void**)&k, g_k);
    cudaGetSymbolAddress((void**)&v, g_v);
    cudaGetSymbolAddress((void**)&o, g_o);
    cudaGetSymbolAddress((void**)&f, g_f);
    cudaGetSymbolAddress((void**)&whi, g_whi);
    float* p0 = p;
    float* p1 = p + (size_t)Mq_ * Dq_;
    float* p2 = p + 2 * (size_t)Mq_ * Dq_;

    cudaFuncSetAttribute((const void*)gemm_kernel<0,true>,  cudaFuncAttributeMaxDynamicSharedMemorySize, GEMM_SMEM);
    cudaFuncSetAttribute((const void*)gemm_kernel<1,false>, cudaFuncAttributeMaxDynamicSharedMemorySize, GEMM_SMEM);
    cudaFuncSetAttribute((const void*)gemm_kernel<4,false>, cudaFuncAttributeMaxDynamicSharedMemorySize, GEMM_SMEM);
    cudaFuncSetAttribute((const void*)gemm_qkv_kernel, cudaFuncAttributeMaxDynamicSharedMemorySize, GEMM_SMEM);
    cudaFuncSetAttribute((const void*)attn_kernel, cudaFuncAttributeMaxDynamicSharedMemorySize, ATTN_SMEM);

    // ---- weight prep (batched, fp16 1-term) ----
    dim3 tb(32, 8);
    tsplit_sq_kernel<<<dim3(24, 24, 48), tb>>>(Wq, Wk, Wv, Wo, whi);
    tsplit_w1_kernel<<<dim3(Hq_ / 32, 24, 12), tb>>>(W1, whi);
    tsplit_w2_kernel<<<dim3(24, Hq_ / 32, 12), tb>>>(W2, whi);
    tsplit_out_kernel<<<dim3(VPAD_ / 32, 24), tb>>>(Wout, whi);

    embed_kernel<<<Mq_, 256>>>(x, tok, pos, h);

    dim3 gQKV(Dq_ / 128, Mq_ / 128, 3);
    dim3 gDs3(Dq_ / 128, Mq_ / 128, 3);
    dim3 gH(Hq_ / 128, Mq_ / 128);
    dim3 gVsw(Mq_ / 128, VPAD_ / 128);
    dim3 gAtt(Sq_ / 64, NHq_, Bq_);
    const int LNG = Mq_ / 8;

    for (int i = 0; i < Lq_; ++i) {
        size_t off = (size_t)i * LWBLK;
        if (i == 0)
            ln_warp_kernel<false,false><<<LNG, 256>>>(h, nullptr, nullptr, nullptr, ln1w, ln1b, a);
        else
            ln_warp_kernel<true,true><<<LNG, 256>>>(h, p0, p1, p2, ln1w + i * Dq_, ln1b + i * Dq_, a);

        gemm_qkv_kernel<<<gQKV, 256, GEMM_SMEM>>>(a, whi + off,
            bq + i * Dq_, bk + i * Dq_, bv + i * Dq_, q, k, v);
        attn_kernel<<<gAtt, 128, ATTN_SMEM>>>(q, k, v, o);

        gemm_kernel<4,false><<<gDs3, 256, GEMM_SMEM>>>(o, whi + off + 3 * WSQ,
            bo + i * Dq_, p, nullptr, Dq_, Dq_, Dq_);

        ln_warp_kernel<true,true><<<LNG, 256>>>(h, p0, p1, p2, ln2w + i * Dq_, ln2b + i * Dq_, a);

        gemm_kernel<1,false><<<gH, 256, GEMM_SMEM>>>(a, whi + off + 4 * WSQ,
            b1 + i * Hq_, nullptr, f, Dq_, Hq_, Hq_);

        gemm_kernel<4,false><<<gDs3, 256, GEMM_SMEM>>>(f, whi + off + 4 * WSQ + WSH,
            b2 + i * Dq_, p, nullptr, Hq_, Dq_, Dq_);
    }

    ln_warp_kernel<true,false><<<LNG, 256>>>(h, p0, p1, p2, lnfw, lnfb, a);
    gemm_kernel<0,true><<<gVsw, 256, GEMM_SMEM>>>(a, whi + WOUT_OFF,
        bout, out, nullptr, Dq_, VPAD_, Vq_);
}

// round 15
// speedup vs baseline: 1.4183x; 1.0139x over previous
#include <cuda_runtime.h>
#include <cuda_fp16.h>
#include <math.h>
#include <stdint.h>

// ---------------- problem constants ----------------
#define Bq_ 4
#define Sq_ 1024
#define Vq_ 50257
#define VPAD_ 50304
#define Dq_ 768
#define Hq_ 3072
#define NHq_ 12
#define DHq_ 64
#define Lq_ 12
#define Mq_ (Bq_*Sq_)   // 4096 rows

typedef __half f16;

#define WSQ (768UL*768UL)
#define WSH (768UL*3072UL)
#define LWBLK (4UL*WSQ + 2UL*WSH)
#define WOUT_OFF (LWBLK*12UL)
#define WTOT (WOUT_OFF + (size_t)VPAD_*Dq_)

// ---------------- scratch (device globals; no allocs allowed) ----------------
__device__ float g_h[Mq_*Dq_];
__device__ float g_p[3UL*Mq_*Dq_];          // split-K3 partial planes
__device__ f16 g_a[Mq_*Dq_];
__device__ f16 g_q[Mq_*Dq_];
__device__ f16 g_k[Mq_*Dq_];
__device__ f16 g_v[Mq_*Dq_];
__device__ f16 g_o[Mq_*Dq_];
__device__ f16 g_f[Mq_*Hq_];
__device__ f16 g_whi[WTOT];

// ---------------- helpers ----------------
__device__ __forceinline__ uint32_t s2u(const void* p) {
    return (uint32_t)__cvta_generic_to_shared(p);
}
__device__ __forceinline__ void cp16(uint32_t d, const void* s) {
    asm volatile("cp.async.cg.shared.global [%0], [%1], 16;\n" :: "r"(d), "l"(s) : "memory");
}
#define CP_COMMIT asm volatile("cp.async.commit_group;\n" ::: "memory")
#define CP_WAIT1  asm volatile("cp.async.wait_group 1;\n" ::: "memory")
#define CP_WAIT0  asm volatile("cp.async.wait_group 0;\n" ::: "memory")

__device__ __forceinline__ void ldsm4(uint32_t &r0, uint32_t &r1, uint32_t &r2, uint32_t &r3,
                                      uint32_t addr) {
    asm volatile("ldmatrix.sync.aligned.m8n8.x4.shared.b16 {%0,%1,%2,%3}, [%4];\n"
        : "=r"(r0), "=r"(r1), "=r"(r2), "=r"(r3) : "r"(addr));
}
__device__ __forceinline__ void ldsm4t(uint32_t &r0, uint32_t &r1, uint32_t &r2, uint32_t &r3,
                                       uint32_t addr) {
    asm volatile("ldmatrix.sync.aligned.m8n8.x4.trans.shared.b16 {%0,%1,%2,%3}, [%4];\n"
        : "=r"(r0), "=r"(r1), "=r"(r2), "=r"(r3) : "r"(addr));
}
__device__ __forceinline__ void mma_f16(float* c, uint32_t a0, uint32_t a1, uint32_t a2, uint32_t a3,
                                        uint32_t b0, uint32_t b1) {
    asm volatile("mma.sync.aligned.m16n8k16.row.col.f32.f16.f16.f32 "
        "{%0,%1,%2,%3},{%4,%5,%6,%7},{%8,%9},{%0,%1,%2,%3};\n"
        : "+f"(c[0]), "+f"(c[1]), "+f"(c[2]), "+f"(c[3])
        : "r"(a0), "r"(a1), "r"(a2), "r"(a3), "r"(b0), "r"(b1));
}
__device__ __forceinline__ uint32_t packh2(float a, float b) {
    __half2 t = __floats2half2_rn(a, b);
    return *(uint32_t*)&t;
}

// ---------------- weight transpose (fp16, 1-term), batched, coalesced writes ----------------
__device__ __forceinline__ void tsplit_body(const float* __restrict__ W, f16* __restrict__ hi,
                                            int K, int Nsrc) {
    __shared__ float tile[32][33];   // [k][n]
    int k0 = blockIdx.y * 32, n0 = blockIdx.x * 32;
    int tid = threadIdx.y * 32 + threadIdx.x;
    int tx = threadIdx.x, ty = threadIdx.y;
    #pragma unroll
    for (int i = 0; i < 4; i++) {
        int k = k0 + ty + i * 8, n = n0 + tx;
        tile[ty + i * 8][tx] = (n < Nsrc) ? W[(long)k * Nsrc + n] : 0.f;
    }
    __syncthreads();
    // packed writes: __half2 along K (contiguous in hi)
    #pragma unroll
    for (int i = 0; i < 2; i++) {
        int n_l = (tid >> 4) + i * 16;
        int kp = (tid & 15) * 2;
        __half2 hv = __floats2half2_rn(tile[kp][n_l], tile[kp + 1][n_l]);
        *(__half2*)&hi[(long)(n0 + n_l) * K + k0 + kp] = hv;
    }
}

__global__ void tsplit_sq_kernel(const float* __restrict__ Wq, const float* __restrict__ Wk,
                                 const float* __restrict__ Wv, const float* __restrict__ Wo,
                                 f16* __restrict__ hi) {
    int z = blockIdx.z, layer = z >> 2, which = z & 3;
    const float* W = (which == 0 ? Wq : which == 1 ? Wk : which == 2 ? Wv : Wo) + (size_t)layer * WSQ;
    size_t off = (size_t)layer * LWBLK + (size_t)which * WSQ;
    tsplit_body(W, hi + off, 768, 768);
}
__global__ void tsplit_w1_kernel(const float* __restrict__ W1, f16* __restrict__ hi) {
    int layer = blockIdx.z;
    size_t off = (size_t)layer * LWBLK + 4 * WSQ;
    tsplit_body(W1 + (size_t)layer * WSH, hi + off, 768, Hq_);
}
__global__ void tsplit_w2_kernel(const float* __restrict__ W2, f16* __restrict__ hi) {
    int layer = blockIdx.z;
    size_t off = (size_t)layer * LWBLK + 4 * WSQ + WSH;
    tsplit_body(W2 + (size_t)layer * WSH, hi + off, Hq_, 768);
}
__global__ void tsplit_out_kernel(const float* __restrict__ W, f16* __restrict__ hi) {
    tsplit_body(W, hi + WOUT_OFF, 768, Vq_);
}

// ---------------- embedding ----------------
__global__ void embed_kernel(const int* __restrict__ x,
                             const float* __restrict__ tok,
                             const float* __restrict__ pos,
                             float* __restrict__ h) {
    int row = blockIdx.x;
    int s = row & (Sq_ - 1);
    int tid = x[row];
    const float* tp = tok + (long)tid * Dq_;
    const float* pp = pos + (long)s * Dq_;
    float* hp = h + (long)row * Dq_;
    for (int d = threadIdx.x; d < Dq_; d += 256)
        hp[d] = tp[d] + pp[d];
}

// ---------------- warp-per-row layernorm (+ optional partial-plane sum) ----------------
template<bool SUM, bool WRITEH>
__global__ __launch_bounds__(256) void ln_warp_kernel(
    float* __restrict__ H,
    const float* __restrict__ P0, const float* __restrict__ P1, const float* __restrict__ P2,
    const float* __restrict__ w, const float* __restrict__ bb,
    f16* __restrict__ Y)
{
    int warp = threadIdx.x >> 5, lane = threadIdx.x & 31;
    long base = ((long)blockIdx.x * 8 + warp) * Dq_;

    float4 v[6];
    #pragma unroll
    for (int j = 0; j < 6; j++) {
        int idx = (lane + j * 32) * 4;
        float4 hv = *(const float4*)&H[base + idx];
        if (SUM) {
            float4 a0 = *(const float4*)&P0[base + idx];
            float4 a1 = *(const float4*)&P1[base + idx];
            float4 a2 = *(const float4*)&P2[base + idx];
            hv.x += a0.x + a1.x + a2.x;
            hv.y += a0.y + a1.y + a2.y;
            hv.z += a0.z + a1.z + a2.z;
            hv.w += a0.w + a1.w + a2.w;
            if (WRITEH) *(float4*)&H[base + idx] = hv;
        }
        v[j] = hv;
    }

    float s = 0.f;
    #pragma unroll
    for (int j = 0; j < 6; j++) s += v[j].x + v[j].y + v[j].z + v[j].w;
    #pragma unroll
    for (int o = 16; o > 0; o >>= 1) s += __shfl_xor_sync(0xffffffffu, s, o);
    float mean = s * (1.0f / Dq_);

    float q = 0.f;
    #pragma unroll
    for (int j = 0; j < 6; j++) {
        v[j].x -= mean; v[j].y -= mean; v[j].z -= mean; v[j].w -= mean;
        q += v[j].x * v[j].x + v[j].y * v[j].y + v[j].z * v[j].z + v[j].w * v[j].w;
    }
    #pragma unroll
    for (int o = 16; o > 0; o >>= 1) q += __shfl_xor_sync(0xffffffffu, q, o);
    float inv = rsqrtf(q * (1.0f / Dq_) + 1e-5f);

    #pragma unroll
    for (int j = 0; j < 6; j++) {
        int idx = (lane + j * 32) * 4;
        float4 wv = *(const float4*)&w[idx];
        float4 bv = *(const float4*)&bb[idx];
        uint2 outp;
        outp.x = packh2(v[j].x * inv * wv.x + bv.x, v[j].y * inv * wv.y + bv.y);
        outp.y = packh2(v[j].z * inv * wv.z + bv.z, v[j].w * inv * wv.w + bv.w);
        *(uint2*)&Y[base + idx] = outp;
    }
}

// ---------------- fp16 HMMA GEMM, 1-term, 3-stage pipeline, 128x64 tile, 3 CTAs/SM ----------------
// C = A[MxK](f16) * Bh^T + bias
// EPI: 0 = fp32 C+bias; 1 = GELU -> f16; 3 = f16 out; 4 = split-K3 fp32 partial plane
#define ABUF (128 * 40)
#define BBUF (64 * 40)
#define BUFH (ABUF + BBUF)                 // halves per stage
#define GEMM_SMEM (3 * BUFH * 2)           // 46080 bytes

template<int EPI, bool SWAP>
__device__ __forceinline__ void gemm_body(
    const f16* __restrict__ A,
    const f16* __restrict__ Bhi,
    const float* __restrict__ bias,
    float* __restrict__ C, f16* __restrict__ C16,
    int K, int N, int Nout)
{
    extern __shared__ f16 sm[];    // [3 buf][A 128x40 | B 64x40]
    uint32_t smb = s2u(sm);
    int tid = threadIdx.x;
    int bm = (SWAP ? blockIdx.x : blockIdx.y) * 128;
    int bn = (SWAP ? blockIdx.y : blockIdx.x) * 64;
    int warp = tid >> 5, lane = tid & 31;
    int wm = warp >> 1, wn = warp & 1;   // 4 x 2 warps -> 32x32 warp tiles

    int kz = (EPI == 4) ? blockIdx.z : 0;
    int Keff = (EPI == 4) ? (K / 3) : K;
    long koff = (long)kz * Keff;

    float acc[2][4][4];
    #pragma unroll
    for (int i = 0; i < 2; i++)
        #pragma unroll
        for (int j = 0; j < 4; j++)
            #pragma unroll
            for (int k = 0; k < 4; k++) acc[i][j][k] = 0.f;

    const f16* Asrc = A + (long)bm * K + koff;
    const f16* Bsrc = Bhi + (long)bn * K + koff;

    auto issue = [&](int b, int kt) {
        int k0 = kt * 32;
        // A: 512 chunks (128 rows x 4), 2 per thread
        #pragma unroll
        for (int i = 0; i < 2; i++) {
            int ch = tid + i * 256;
            int row = ch >> 2, cg = ch & 3;
            uint32_t dst = smb + (uint32_t)(b * BUFH + row * 40 + cg * 8) * 2;
            cp16(dst, Asrc + (long)row * K + k0 + cg * 8);
        }
        // B: 256 chunks (64 rows x 4), 1 per thread
        {
            int row = tid >> 2, cg = tid & 3;
            uint32_t dst = smb + (uint32_t)(b * BUFH + ABUF + row * 40 + cg * 8) * 2;
            cp16(dst, Bsrc + (long)row * K + k0 + cg * 8);
        }
    };

    int nk = Keff >> 5;
    issue(0, 0); CP_COMMIT;
    issue(1, 1); CP_COMMIT;

    int lrow = lane & 15, lcg = lane >> 4;

    for (int kt = 0; kt < nk; ++kt) {
        int cur = kt % 3;
        if (kt + 1 < nk) { CP_WAIT1; } else { CP_WAIT0; }
        __syncthreads();
        if (kt + 2 < nk) { issue((kt + 2) % 3, kt + 2); CP_COMMIT; }

        #pragma unroll
        for (int ks = 0; ks < 2; ++ks) {
            int col = ks * 16 + lcg * 8;
            uint32_t af[2][4];
            #pragma unroll
            for (int mf = 0; mf < 2; mf++) {
                int row = wm * 32 + mf * 16 + lrow;
                uint32_t a0 = smb + (uint32_t)(cur * BUFH + row * 40 + col) * 2;
                ldsm4(af[mf][0], af[mf][1], af[mf][2], af[mf][3], a0);
            }
            uint32_t bh[2][4];
            #pragma unroll
            for (int nf2 = 0; nf2 < 2; nf2++) {
                int row = wn * 32 + nf2 * 16 + lrow;
                uint32_t b0 = smb + (uint32_t)(cur * BUFH + ABUF + row * 40 + col) * 2;
                ldsm4(bh[nf2][0], bh[nf2][1], bh[nf2][2], bh[nf2][3], b0);
            }
            #pragma unroll
            for (int mf = 0; mf < 2; mf++)
                #pragma unroll
                for (int nf = 0; nf < 4; nf++) {
                    int g = nf >> 1, o = nf & 1;
                    mma_f16(acc[mf][nf], af[mf][0], af[mf][1], af[mf][2], af[mf][3],
                            bh[g][o], bh[g][o + 2]);
                }
        }
    }

    float* Cp = (EPI == 4) ? (C + (size_t)kz * Mq_ * (size_t)Nout) : C;

    int r = lane >> 2, c2 = (lane & 3) * 2;
    #pragma unroll
    for (int mf = 0; mf < 2; mf++) {
        #pragma unroll
        for (int nf = 0; nf < 4; nf++) {
            #pragma unroll
            for (int half2_ = 0; half2_ < 2; half2_++) {
                long row = bm + wm * 32 + mf * 16 + r + half2_ * 8;
                #pragma unroll
                for (int e = 0; e < 2; e++) {
                    int col = bn + wn * 32 + nf * 8 + c2 + e;
                    if (col < Nout) {
                        float v = acc[mf][nf][half2_ * 2 + e];
                        if (EPI == 4) {
                            if (kz == 0) v += bias[col];
                            Cp[row * (long)Nout + col] = v;
                        } else {
                            v += bias[col];
                            if (EPI == 1 || EPI == 3) {
                                if (EPI == 1)
                                    v = 0.5f * v * (1.f + erff(v * 0.70710678118654752f));
                                C16[row * N + col] = __float2half_rn(v);
                            } else {
                                Cp[row * (long)Nout + col] = v;
                            }
                        }
                    }
                }
            }
        }
    }
}

template<int EPI, bool SWAP>
__global__ __launch_bounds__(256, 3) void gemm_kernel(
    const f16* __restrict__ A,
    const f16* __restrict__ Bhi,
    const float* __restrict__ bias,
    float* __restrict__ C, f16* __restrict__ C16,
    int K, int N, int Nout)
{
    gemm_body<EPI, SWAP>(A, Bhi, bias, C, C16, K, N, Nout);
}

// fused QKV (all 1-term), blockIdx.z selects q/k/v
__global__ __launch_bounds__(256, 3) void gemm_qkv_kernel(
    const f16* __restrict__ A,
    const f16* __restrict__ whi,
    const float* __restrict__ bq, const float* __restrict__ bk, const float* __restrict__ bv,
    f16* __restrict__ q, f16* __restrict__ k, f16* __restrict__ v)
{
    int z = blockIdx.z;
    const f16* Bh = whi + (size_t)z * WSQ;
    const float* bias = (z == 0) ? bq : (z == 1) ? bk : bv;
    f16* C16 = (z == 0) ? q : (z == 1) ? k : v;
    gemm_body<3, false>(A, Bh, bias, nullptr, C16, Dq_, Dq_, Dq_);
}

// ---------------- HMMA flash attention, fp16, double-buffered, heavy-first ----------------
#define AT_STRIDE 72
#define AT_TILE (64 * AT_STRIDE)
#define ATTN_SMEM (5 * AT_TILE * 2)   // Q + 2x(K,V) = 46080

__global__ __launch_bounds__(128, 4) void attn_kernel(
    const f16* __restrict__ Qg, const f16* __restrict__ Kg, const f16* __restrict__ Vg,
    f16* __restrict__ O)
{
    extern __shared__ f16 asm_[];
    uint32_t smb = s2u(asm_);
    uint32_t sQ = smb;

    int t = threadIdx.x, warp = t >> 5, lane = t & 31;
    int qt = (int)gridDim.x - 1 - (int)blockIdx.x;   // LPT: heavy first
    int q0 = qt * 64, h = blockIdx.y, b = blockIdx.z;

    long rowbase = (long)(b * Sq_ + q0) * Dq_ + h * DHq_;

    auto issue_kv = [&](int buf, int jt) {
        uint32_t sK = smb + (1 + buf * 2) * AT_TILE * 2;
        uint32_t sV = sK + AT_TILE * 2;
        long kbase = (long)(b * Sq_ + jt * 64) * Dq_ + h * DHq_;
        #pragma unroll
        for (int i = 0; i < 4; i++) {
            int idx = t + i * 128;
            int row = idx >> 3, ch = idx & 7;
            uint32_t doff = (uint32_t)(row * AT_STRIDE + ch * 8) * 2;
            long goff = kbase + (long)row * Dq_ + ch * 8;
            cp16(sK + doff, Kg + goff);
            cp16(sV + doff, Vg + goff);
        }
    };

    #pragma unroll
    for (int i = 0; i < 4; i++) {
        int idx = t + i * 128;
        int row = idx >> 3, ch = idx & 7;
        uint32_t doff = (uint32_t)(row * AT_STRIDE + ch * 8) * 2;
        cp16(sQ + doff, Qg + rowbase + (long)row * Dq_ + ch * 8);
    }
    issue_kv(0, 0);
    CP_COMMIT;

    float m[2] = { -1e30f, -1e30f }, l[2] = { 0.f, 0.f };
    float oacc[8][4];
    #pragma unroll
    for (int i = 0; i < 8; i++)
        #pragma unroll
        for (int j = 0; j < 4; j++) oacc[i][j] = 0.f;

    int lrow = lane & 15, lcg = lane >> 4;
    int ntiles = q0 / 64 + 1;

    for (int it = 0; it < ntiles; ++it) {
        if (it + 1 < ntiles) { issue_kv((it + 1) & 1, it + 1); CP_COMMIT; CP_WAIT1; }
        else                 { CP_WAIT0; }
        __syncthreads();

        uint32_t sK = smb + (1 + (it & 1) * 2) * AT_TILE * 2;
        uint32_t sV = sK + AT_TILE * 2;
        int j0 = it * 64;

        float sacc[8][4];
        #pragma unroll
        for (int i = 0; i < 8; i++)
            #pragma unroll
            for (int j = 0; j < 4; j++) sacc[i][j] = 0.f;

        #pragma unroll
        for (int ks = 0; ks < 4; ++ks) {
            int acol = ks * 16 + lcg * 8;
            uint32_t qf[4];
            uint32_t qaddr = (uint32_t)((warp * 16 + lrow) * AT_STRIDE + acol) * 2;
            ldsm4(qf[0], qf[1], qf[2], qf[3], sQ + qaddr);
            uint32_t kf[4][4];
            #pragma unroll
            for (int kg = 0; kg < 4; ++kg) {
                uint32_t kaddr = (uint32_t)((kg * 16 + lrow) * AT_STRIDE + acol) * 2;
                ldsm4(kf[kg][0], kf[kg][1], kf[kg][2], kf[kg][3], sK + kaddr);
            }
            #pragma unroll
            for (int kg = 0; kg < 4; ++kg)
                #pragma unroll
                for (int o = 0; o < 2; ++o)
                    mma_f16(sacc[kg * 2 + o], qf[0], qf[1], qf[2], qf[3], kf[kg][o], kf[kg][o + 2]);
        }

        int r0loc = warp * 16 + (lane >> 2);
        bool diag = (j0 == q0);
        float mx[2] = { -1e30f, -1e30f };
        #pragma unroll
        for (int nf = 0; nf < 8; nf++) {
            #pragma unroll
            for (int i = 0; i < 4; i++) {
                float v = sacc[nf][i] * 0.125f;
                if (diag) {
                    int col = nf * 8 + (lane & 3) * 2 + (i & 1);
                    int row = r0loc + ((i >> 1) ? 8 : 0);
                    if (col > row) v = -1e30f;
                }
                sacc[nf][i] = v;
                mx[i >> 1] = fmaxf(mx[i >> 1], v);
            }
        }
        #pragma unroll
        for (int o = 1; o < 4; o <<= 1) {
            mx[0] = fmaxf(mx[0], __shfl_xor_sync(0xffffffffu, mx[0], o));
            mx[1] = fmaxf(mx[1], __shfl_xor_sync(0xffffffffu, mx[1], o));
        }
        float fac[2], sum[2] = { 0.f, 0.f };
        #pragma unroll
        for (int j = 0; j < 2; j++) {
            float mnew = fmaxf(m[j], mx[j]);
            fac[j] = __expf(m[j] - mnew);
            m[j] = mnew;
        }
        #pragma unroll
        for (int nf = 0; nf < 8; nf++) {
            #pragma unroll
            for (int i = 0; i < 4; i++) {
                float p = __expf(sacc[nf][i] - m[i >> 1]);
                sacc[nf][i] = p;
                sum[i >> 1] += p;
            }
        }
        #pragma unroll
        for (int o = 1; o < 4; o <<= 1) {
            sum[0] += __shfl_xor_sync(0xffffffffu, sum[0], o);
            sum[1] += __shfl_xor_sync(0xffffffffu, sum[1], o);
        }
        #pragma unroll
        for (int j = 0; j < 2; j++) l[j] = l[j] * fac[j] + sum[j];
        #pragma unroll
        for (int nf = 0; nf < 8; nf++) {
            oacc[nf][0] *= fac[0]; oacc[nf][1] *= fac[0];
            oacc[nf][2] *= fac[1]; oacc[nf][3] *= fac[1];
        }

        #pragma unroll
        for (int t2 = 0; t2 < 4; ++t2) {
            float* p0 = sacc[2 * t2];
            float* p1 = sacc[2 * t2 + 1];
            uint32_t pa[4];
            pa[0] = packh2(p0[0], p0[1]);
            pa[1] = packh2(p0[2], p0[3]);
            pa[2] = packh2(p1[0], p1[1]);
            pa[3] = packh2(p1[2], p1[3]);

            uint32_t vf[4][4];
            #pragma unroll
            for (int nd = 0; nd < 4; ++nd) {
                uint32_t vrow = (uint32_t)(t2 * 16 + ((lane >> 4) << 3) + (lane & 7));
                uint32_t vcol = (uint32_t)(nd * 16 + (((lane >> 3) & 1) << 3));
                uint32_t vaddr = (vrow * AT_STRIDE + vcol) * 2;
                ldsm4t(vf[nd][0], vf[nd][1], vf[nd][2], vf[nd][3], sV + vaddr);
            }
            #pragma unroll
            for (int nd = 0; nd < 4; ++nd)
                #pragma unroll
                for (int o = 0; o < 2; ++o)
                    mma_f16(oacc[nd * 2 + o], pa[0], pa[1], pa[2], pa[3], vf[nd][o], vf[nd][o + 2]);
        }
        __syncthreads();
    }

    float inv0 = 1.f / l[0], inv1 = 1.f / l[1];
    long row0 = (long)(b * Sq_ + q0 + warp * 16 + (lane >> 2));
    long row1 = row0 + 8;
    #pragma unroll
    for (int nf = 0; nf < 8; nf++) {
        int col = h * DHq_ + nf * 8 + (lane & 3) * 2;
        *(__half2*)&O[row0 * Dq_ + col] = __floats2half2_rn(oacc[nf][0] * inv0, oacc[nf][1] * inv0);
        *(__half2*)&O[row1 * Dq_ + col] = __floats2half2_rn(oacc[nf][2] * inv1, oacc[nf][3] * inv1);
    }
}

// ---------------- launcher ----------------
extern "C" void kernel_launch(void* const* d_in, const int* in_sizes, int n_in,
                              void* d_out, int out_size) {
    const int*   x    = (const int*)  d_in[0];
    const float* tok  = (const float*)d_in[1];
    const float* pos  = (const float*)d_in[2];
    const float* Wq   = (const float*)d_in[3];
    const float* bq   = (const float*)d_in[4];
    const float* Wk   = (const float*)d_in[5];
    const float* bk   = (const float*)d_in[6];
    const float* Wv   = (const float*)d_in[7];
    const float* bv   = (const float*)d_in[8];
    const float* Wo   = (const float*)d_in[9];
    const float* bo   = (const float*)d_in[10];
    const float* ln1w = (const float*)d_in[11];
    const float* ln1b = (const float*)d_in[12];
    const float* ln2w = (const float*)d_in[13];
    const float* ln2b = (const float*)d_in[14];
    const float* W1   = (const float*)d_in[15];
    const float* b1   = (const float*)d_in[16];
    const float* W2   = (const float*)d_in[17];
    const float* b2   = (const float*)d_in[18];
    const float* lnfw = (const float*)d_in[19];
    const float* lnfb = (const float*)d_in[20];
    const float* Wout = (const float*)d_in[21];
    const float* bout = (const float*)d_in[22];
    float* out = (float*)d_out;

    float *h, *p;
    f16 *a, *q, *k, *v, *o, *f, *whi;
    cudaGetSymbolAddress((void**)&h, g_h);
    cudaGetSymbolAddress((void**)&p, g_p);
    cudaGetSymbolAddress((void**)&a, g_a);
    cudaGetSymbolAddress((void**)&q, g_q);
    cudaGetSymbolAddress((void**)&k, g_k);
    cudaGetSymbolAddress((void**)&v, g_v);
    cudaGetSymbolAddress((void**)&o, g_o);
    cudaGetSymbolAddress((void**)&f, g_f);
    cudaGetSymbolAddress((void**)&whi, g_whi);
    float* p0 = p;
    float* p1 = p + (size_t)Mq_ * Dq_;
    float* p2 = p + 2 * (size_t)Mq_ * Dq_;

    cudaFuncSetAttribute((const void*)gemm_kernel<0,true>,  cudaFuncAttributeMaxDynamicSharedMemorySize, GEMM_SMEM);
    cudaFuncSetAttribute((const void*)gemm_kernel<1,false>, cudaFuncAttributeMaxDynamicSharedMemorySize, GEMM_SMEM);
    cudaFuncSetAttribute((const void*)gemm_kernel<4,false>, cudaFuncAttributeMaxDynamicSharedMemorySize, GEMM_SMEM);
    cudaFuncSetAttribute((const void*)gemm_qkv_kernel, cudaFuncAttributeMaxDynamicSharedMemorySize, GEMM_SMEM);
    cudaFuncSetAttribute((const void*)attn_kernel, cudaFuncAttributeMaxDynamicSharedMemorySize, ATTN_SMEM);

    // ---- weight prep (batched, fp16 1-term) ----
    dim3 tb(32, 8);
    tsplit_sq_kernel<<<dim3(24, 24, 48), tb>>>(Wq, Wk, Wv, Wo, whi);
    tsplit_w1_kernel<<<dim3(Hq_ / 32, 24, 12), tb>>>(W1, whi);
    tsplit_w2_kernel<<<dim3(24, Hq_ / 32, 12), tb>>>(W2, whi);
    tsplit_out_kernel<<<dim3(VPAD_ / 32, 24), tb>>>(Wout, whi);

    embed_kernel<<<Mq_, 256>>>(x, tok, pos, h);

    dim3 gQKV(Dq_ / 64, Mq_ / 128, 3);    // 12 x 32 x 3
    dim3 gDs3(Dq_ / 64, Mq_ / 128, 3);    // split-K3, 12 x 32 x 3
    dim3 gH(Hq_ / 64, Mq_ / 128);         // 48 x 32
    dim3 gVsw(Mq_ / 128, VPAD_ / 64);     // 32 x 786 (SWAP)
    dim3 gAtt(Sq_ / 64, NHq_, Bq_);
    const int LNG = Mq_ / 8;

    for (int i = 0; i < Lq_; ++i) {
        size_t off = (size_t)i * LWBLK;
        if (i == 0)
            ln_warp_kernel<false,false><<<LNG, 256>>>(h, nullptr, nullptr, nullptr, ln1w, ln1b, a);
        else
            ln_warp_kernel<true,true><<<LNG, 256>>>(h, p0, p1, p2, ln1w + i * Dq_, ln1b + i * Dq_, a);

        gemm_qkv_kernel<<<gQKV, 256, GEMM_SMEM>>>(a, whi + off,
            bq + i * Dq_, bk + i * Dq_, bv + i * Dq_, q, k, v);
        attn_kernel<<<gAtt, 128, ATTN_SMEM>>>(q, k, v, o);

        gemm_kernel<4,false><<<gDs3, 256, GEMM_SMEM>>>(o, whi + off + 3 * WSQ,
            bo + i * Dq_, p, nullptr, Dq_, Dq_, Dq_);

        ln_warp_kernel<true,true><<<LNG, 256>>>(h, p0, p1, p2, ln2w + i * Dq_, ln2b + i * Dq_, a);

        gemm_kernel<1,false><<<gH, 256, GEMM_SMEM>>>(a, whi + off + 4 * WSQ,
            b1 + i * Hq_, nullptr, f, Dq_, Hq_, Hq_);

        gemm_kernel<4,false><<<gDs3, 256, GEMM_SMEM>>>(f, whi + off + 4 * WSQ + WSH,
            b2 + i * Dq_, p, nullptr, Hq_, Dq_, Dq_);
    }

    ln_warp_kernel<true,false><<<LNG, 256>>>(h, p0, p1, p2, lnfw, lnfb, a);
    gemm_kernel<0,true><<<gVsw, 256, GEMM_SMEM>>>(a, whi + WOUT_OFF,
        bout, out, nullptr, Dq_, VPAD_, Vq_);
}

// round 16
// speedup vs baseline: 1.4302x; 1.0084x over previous
#include <cuda_runtime.h>
#include <cuda_fp16.h>
#include <math.h>
#include <stdint.h>

// ---------------- problem constants ----------------
#define Bq_ 4
#define Sq_ 1024
#define Vq_ 50257
#define VPAD_ 50304
#define Dq_ 768
#define Hq_ 3072
#define NHq_ 12
#define DHq_ 64
#define Lq_ 12
#define Mq_ (Bq_*Sq_)   // 4096 rows

typedef __half f16;

#define WSQ (768UL*768UL)
#define WSH (768UL*3072UL)
#define LWBLK (4UL*WSQ + 2UL*WSH)
#define WOUT_OFF (LWBLK*12UL)
#define WTOT (WOUT_OFF + (size_t)VPAD_*Dq_)

// ---------------- scratch (device globals; no allocs allowed) ----------------
__device__ float g_h[Mq_*Dq_];
__device__ f16 g_a[Mq_*Dq_];
__device__ f16 g_q[Mq_*Dq_];
__device__ f16 g_k[Mq_*Dq_];
__device__ f16 g_v[Mq_*Dq_];
__device__ f16 g_o[Mq_*Dq_];
__device__ f16 g_f[Mq_*Hq_];
__device__ f16 g_whi[WTOT];

// ---------------- helpers ----------------
__device__ __forceinline__ uint32_t s2u(const void* p) {
    return (uint32_t)__cvta_generic_to_shared(p);
}
__device__ __forceinline__ void cp16(uint32_t d, const void* s) {
    asm volatile("cp.async.cg.shared.global [%0], [%1], 16;\n" :: "r"(d), "l"(s) : "memory");
}
#define CP_COMMIT asm volatile("cp.async.commit_group;\n" ::: "memory")
#define CP_WAIT1  asm volatile("cp.async.wait_group 1;\n" ::: "memory")
#define CP_WAIT0  asm volatile("cp.async.wait_group 0;\n" ::: "memory")

__device__ __forceinline__ void ldsm4(uint32_t &r0, uint32_t &r1, uint32_t &r2, uint32_t &r3,
                                      uint32_t addr) {
    asm volatile("ldmatrix.sync.aligned.m8n8.x4.shared.b16 {%0,%1,%2,%3}, [%4];\n"
        : "=r"(r0), "=r"(r1), "=r"(r2), "=r"(r3) : "r"(addr));
}
__device__ __forceinline__ void ldsm4t(uint32_t &r0, uint32_t &r1, uint32_t &r2, uint32_t &r3,
                                       uint32_t addr) {
    asm volatile("ldmatrix.sync.aligned.m8n8.x4.trans.shared.b16 {%0,%1,%2,%3}, [%4];\n"
        : "=r"(r0), "=r"(r1), "=r"(r2), "=r"(r3) : "r"(addr));
}
__device__ __forceinline__ void mma_f16(float* c, uint32_t a0, uint32_t a1, uint32_t a2, uint32_t a3,
                                        uint32_t b0, uint32_t b1) {
    asm volatile("mma.sync.aligned.m16n8k16.row.col.f32.f16.f16.f32 "
        "{%0,%1,%2,%3},{%4,%5,%6,%7},{%8,%9},{%0,%1,%2,%3};\n"
        : "+f"(c[0]), "+f"(c[1]), "+f"(c[2]), "+f"(c[3])
        : "r"(a0), "r"(a1), "r"(a2), "r"(a3), "r"(b0), "r"(b1));
}
__device__ __forceinline__ uint32_t packh2(float a, float b) {
    __half2 t = __floats2half2_rn(a, b);
    return *(uint32_t*)&t;
}

// ---------------- weight transpose (fp16, 1-term), batched, coalesced writes ----------------
__device__ __forceinline__ void tsplit_body(const float* __restrict__ W, f16* __restrict__ hi,
                                            int K, int Nsrc) {
    __shared__ float tile[32][33];   // [k][n]
    int k0 = blockIdx.y * 32, n0 = blockIdx.x * 32;
    int tid = threadIdx.y * 32 + threadIdx.x;
    int tx = threadIdx.x, ty = threadIdx.y;
    #pragma unroll
    for (int i = 0; i < 4; i++) {
        int k = k0 + ty + i * 8, n = n0 + tx;
        tile[ty + i * 8][tx] = (n < Nsrc) ? W[(long)k * Nsrc + n] : 0.f;
    }
    __syncthreads();
    #pragma unroll
    for (int i = 0; i < 2; i++) {
        int n_l = (tid >> 4) + i * 16;
        int kp = (tid & 15) * 2;
        __half2 hv = __floats2half2_rn(tile[kp][n_l], tile[kp + 1][n_l]);
        *(__half2*)&hi[(long)(n0 + n_l) * K + k0 + kp] = hv;
    }
}

__global__ void tsplit_sq_kernel(const float* __restrict__ Wq, const float* __restrict__ Wk,
                                 const float* __restrict__ Wv, const float* __restrict__ Wo,
                                 f16* __restrict__ hi) {
    int z = blockIdx.z, layer = z >> 2, which = z & 3;
    const float* W = (which == 0 ? Wq : which == 1 ? Wk : which == 2 ? Wv : Wo) + (size_t)layer * WSQ;
    size_t off = (size_t)layer * LWBLK + (size_t)which * WSQ;
    tsplit_body(W, hi + off, 768, 768);
}
__global__ void tsplit_w1_kernel(const float* __restrict__ W1, f16* __restrict__ hi) {
    int layer = blockIdx.z;
    size_t off = (size_t)layer * LWBLK + 4 * WSQ;
    tsplit_body(W1 + (size_t)layer * WSH, hi + off, 768, Hq_);
}
__global__ void tsplit_w2_kernel(const float* __restrict__ W2, f16* __restrict__ hi) {
    int layer = blockIdx.z;
    size_t off = (size_t)layer * LWBLK + 4 * WSQ + WSH;
    tsplit_body(W2 + (size_t)layer * WSH, hi + off, Hq_, 768);
}
__global__ void tsplit_out_kernel(const float* __restrict__ W, f16* __restrict__ hi) {
    tsplit_body(W, hi + WOUT_OFF, 768, Vq_);
}

// ---------------- embedding ----------------
__global__ void embed_kernel(const int* __restrict__ x,
                             const float* __restrict__ tok,
                             const float* __restrict__ pos,
                             float* __restrict__ h) {
    int row = blockIdx.x;
    int s = row & (Sq_ - 1);
    int tid = x[row];
    const float* tp = tok + (long)tid * Dq_;
    const float* pp = pos + (long)s * Dq_;
    float* hp = h + (long)row * Dq_;
    for (int d = threadIdx.x; d < Dq_; d += 256)
        hp[d] = tp[d] + pp[d];
}

// ---------------- warp-per-row layernorm (plain; residual already in h) ----------------
__global__ __launch_bounds__(256) void ln_warp_kernel(
    const float* __restrict__ H,
    const float* __restrict__ w, const float* __restrict__ bb,
    f16* __restrict__ Y)
{
    int warp = threadIdx.x >> 5, lane = threadIdx.x & 31;
    long base = ((long)blockIdx.x * 8 + warp) * Dq_;

    float4 v[6];
    #pragma unroll
    for (int j = 0; j < 6; j++) {
        int idx = (lane + j * 32) * 4;
        v[j] = *(const float4*)&H[base + idx];
    }

    float s = 0.f;
    #pragma unroll
    for (int j = 0; j < 6; j++) s += v[j].x + v[j].y + v[j].z + v[j].w;
    #pragma unroll
    for (int o = 16; o > 0; o >>= 1) s += __shfl_xor_sync(0xffffffffu, s, o);
    float mean = s * (1.0f / Dq_);

    float q = 0.f;
    #pragma unroll
    for (int j = 0; j < 6; j++) {
        v[j].x -= mean; v[j].y -= mean; v[j].z -= mean; v[j].w -= mean;
        q += v[j].x * v[j].x + v[j].y * v[j].y + v[j].z * v[j].z + v[j].w * v[j].w;
    }
    #pragma unroll
    for (int o = 16; o > 0; o >>= 1) q += __shfl_xor_sync(0xffffffffu, q, o);
    float inv = rsqrtf(q * (1.0f / Dq_) + 1e-5f);

    #pragma unroll
    for (int j = 0; j < 6; j++) {
        int idx = (lane + j * 32) * 4;
        float4 wv = *(const float4*)&w[idx];
        float4 bv = *(const float4*)&bb[idx];
        uint2 outp;
        outp.x = packh2(v[j].x * inv * wv.x + bv.x, v[j].y * inv * wv.y + bv.y);
        outp.y = packh2(v[j].z * inv * wv.z + bv.z, v[j].w * inv * wv.w + bv.w);
        *(uint2*)&Y[base + idx] = outp;
    }
}

// ---------------- fp16 HMMA GEMM, 1-term, 3-stage pipeline, 128x64 tile, 3 CTAs/SM ----------------
// C = A[MxK](f16) * Bh^T + bias
// EPI: 0 = fp32 C+bias; 1 = GELU -> f16; 2 = fp32 residual add in-place; 3 = f16 out
#define ABUF (128 * 40)
#define BBUF (64 * 40)
#define BUFH (ABUF + BBUF)
#define GEMM_SMEM (3 * BUFH * 2)           // 46080 bytes

template<int EPI, bool SWAP>
__device__ __forceinline__ void gemm_body(
    const f16* __restrict__ A,
    const f16* __restrict__ Bhi,
    const float* __restrict__ bias,
    float* __restrict__ C, f16* __restrict__ C16,
    int K, int N, int Nout)
{
    extern __shared__ f16 sm[];
    uint32_t smb = s2u(sm);
    int tid = threadIdx.x;
    int bm = (SWAP ? blockIdx.x : blockIdx.y) * 128;
    int bn = (SWAP ? blockIdx.y : blockIdx.x) * 64;
    int warp = tid >> 5, lane = tid & 31;
    int wm = warp >> 1, wn = warp & 1;

    float acc[2][4][4];
    #pragma unroll
    for (int i = 0; i < 2; i++)
        #pragma unroll
        for (int j = 0; j < 4; j++)
            #pragma unroll
            for (int k = 0; k < 4; k++) acc[i][j][k] = 0.f;

    const f16* Asrc = A + (long)bm * K;
    const f16* Bsrc = Bhi + (long)bn * K;

    auto issue = [&](int b, int kt) {
        int k0 = kt * 32;
        #pragma unroll
        for (int i = 0; i < 2; i++) {
            int ch = tid + i * 256;
            int row = ch >> 2, cg = ch & 3;
            uint32_t dst = smb + (uint32_t)(b * BUFH + row * 40 + cg * 8) * 2;
            cp16(dst, Asrc + (long)row * K + k0 + cg * 8);
        }
        {
            int row = tid >> 2, cg = tid & 3;
            uint32_t dst = smb + (uint32_t)(b * BUFH + ABUF + row * 40 + cg * 8) * 2;
            cp16(dst, Bsrc + (long)row * K + k0 + cg * 8);
        }
    };

    int nk = K >> 5;
    issue(0, 0); CP_COMMIT;
    issue(1, 1); CP_COMMIT;

    int lrow = lane & 15, lcg = lane >> 4;

    for (int kt = 0; kt < nk; ++kt) {
        int cur = kt % 3;
        if (kt + 1 < nk) { CP_WAIT1; } else { CP_WAIT0; }
        __syncthreads();
        if (kt + 2 < nk) { issue((kt + 2) % 3, kt + 2); CP_COMMIT; }

        #pragma unroll
        for (int ks = 0; ks < 2; ++ks) {
            int col = ks * 16 + lcg * 8;
            uint32_t af[2][4];
            #pragma unroll
            for (int mf = 0; mf < 2; mf++) {
                int row = wm * 32 + mf * 16 + lrow;
                uint32_t a0 = smb + (uint32_t)(cur * BUFH + row * 40 + col) * 2;
                ldsm4(af[mf][0], af[mf][1], af[mf][2], af[mf][3], a0);
            }
            uint32_t bh[2][4];
            #pragma unroll
            for (int nf2 = 0; nf2 < 2; nf2++) {
                int row = wn * 32 + nf2 * 16 + lrow;
                uint32_t b0 = smb + (uint32_t)(cur * BUFH + ABUF + row * 40 + col) * 2;
                ldsm4(bh[nf2][0], bh[nf2][1], bh[nf2][2], bh[nf2][3], b0);
            }
            #pragma unroll
            for (int mf = 0; mf < 2; mf++)
                #pragma unroll
                for (int nf = 0; nf < 4; nf++) {
                    int g = nf >> 1, o = nf & 1;
                    mma_f16(acc[mf][nf], af[mf][0], af[mf][1], af[mf][2], af[mf][3],
                            bh[g][o], bh[g][o + 2]);
                }
        }
    }

    int r = lane >> 2, c2 = (lane & 3) * 2;
    #pragma unroll
    for (int mf = 0; mf < 2; mf++) {
        #pragma unroll
        for (int nf = 0; nf < 4; nf++) {
            #pragma unroll
            for (int half2_ = 0; half2_ < 2; half2_++) {
                long row = bm + wm * 32 + mf * 16 + r + half2_ * 8;
                #pragma unroll
                for (int e = 0; e < 2; e++) {
                    int col = bn + wn * 32 + nf * 8 + c2 + e;
                    if (col < Nout) {
                        float v = acc[mf][nf][half2_ * 2 + e] + bias[col];
                        if (EPI == 1 || EPI == 3) {
                            if (EPI == 1)
                                v = 0.5f * v * (1.f + erff(v * 0.70710678118654752f));
                            C16[row * N + col] = __float2half_rn(v);
                        } else if (EPI == 2) {
                            v += C[row * (long)Nout + col];
                            C[row * (long)Nout + col] = v;
                        } else {
                            C[row * (long)Nout + col] = v;
                        }
                    }
                }
            }
        }
    }
}

template<int EPI, bool SWAP>
__global__ __launch_bounds__(256, 3) void gemm_kernel(
    const f16* __restrict__ A,
    const f16* __restrict__ Bhi,
    const float* __restrict__ bias,
    float* __restrict__ C, f16* __restrict__ C16,
    int K, int N, int Nout)
{
    gemm_body<EPI, SWAP>(A, Bhi, bias, C, C16, K, N, Nout);
}

// fused QKV (all 1-term), blockIdx.z selects q/k/v
__global__ __launch_bounds__(256, 3) void gemm_qkv_kernel(
    const f16* __restrict__ A,
    const f16* __restrict__ whi,
    const float* __restrict__ bq, const float* __restrict__ bk, const float* __restrict__ bv,
    f16* __restrict__ q, f16* __restrict__ k, f16* __restrict__ v)
{
    int z = blockIdx.z;
    const f16* Bh = whi + (size_t)z * WSQ;
    const float* bias = (z == 0) ? bq : (z == 1) ? bk : bv;
    f16* C16 = (z == 0) ? q : (z == 1) ? k : v;
    gemm_body<3, false>(A, Bh, bias, nullptr, C16, Dq_, Dq_, Dq_);
}

// ---------------- HMMA flash attention, fp16, double-buffered, heavy-first ----------------
#define AT_STRIDE 72
#define AT_TILE (64 * AT_STRIDE)
#define ATTN_SMEM (5 * AT_TILE * 2)   // Q + 2x(K,V) = 46080

__global__ __launch_bounds__(128, 4) void attn_kernel(
    const f16* __restrict__ Qg, const f16* __restrict__ Kg, const f16* __restrict__ Vg,
    f16* __restrict__ O)
{
    extern __shared__ f16 asm_[];
    uint32_t smb = s2u(asm_);
    uint32_t sQ = smb;

    int t = threadIdx.x, warp = t >> 5, lane = t & 31;
    int qt = (int)gridDim.x - 1 - (int)blockIdx.x;   // LPT: heavy first
    int q0 = qt * 64, h = blockIdx.y, b = blockIdx.z;

    long rowbase = (long)(b * Sq_ + q0) * Dq_ + h * DHq_;

    auto issue_kv = [&](int buf, int jt) {
        uint32_t sK = smb + (1 + buf * 2) * AT_TILE * 2;
        uint32_t sV = sK + AT_TILE * 2;
        long kbase = (long)(b * Sq_ + jt * 64) * Dq_ + h * DHq_;
        #pragma unroll
        for (int i = 0; i < 4; i++) {
            int idx = t + i * 128;
            int row = idx >> 3, ch = idx & 7;
            uint32_t doff = (uint32_t)(row * AT_STRIDE + ch * 8) * 2;
            long goff = kbase + (long)row * Dq_ + ch * 8;
            cp16(sK + doff, Kg + goff);
            cp16(sV + doff, Vg + goff);
        }
    };

    #pragma unroll
    for (int i = 0; i < 4; i++) {
        int idx = t + i * 128;
        int row = idx >> 3, ch = idx & 7;
        uint32_t doff = (uint32_t)(row * AT_STRIDE + ch * 8) * 2;
        cp16(sQ + doff, Qg + rowbase + (long)row * Dq_ + ch * 8);
    }
    issue_kv(0, 0);
    CP_COMMIT;

    float m[2] = { -1e30f, -1e30f }, l[2] = { 0.f, 0.f };
    float oacc[8][4];
    #pragma unroll
    for (int i = 0; i < 8; i++)
        #pragma unroll
        for (int j = 0; j < 4; j++) oacc[i][j] = 0.f;

    int lrow = lane & 15, lcg = lane >> 4;
    int ntiles = q0 / 64 + 1;

    for (int it = 0; it < ntiles; ++it) {
        if (it + 1 < ntiles) { issue_kv((it + 1) & 1, it + 1); CP_COMMIT; CP_WAIT1; }
        else                 { CP_WAIT0; }
        __syncthreads();

        uint32_t sK = smb + (1 + (it & 1) * 2) * AT_TILE * 2;
        uint32_t sV = sK + AT_TILE * 2;
        int j0 = it * 64;

        float sacc[8][4];
        #pragma unroll
        for (int i = 0; i < 8; i++)
            #pragma unroll
            for (int j = 0; j < 4; j++) sacc[i][j] = 0.f;

        #pragma unroll
        for (int ks = 0; ks < 4; ++ks) {
            int acol = ks * 16 + lcg * 8;
            uint32_t qf[4];
            uint32_t qaddr = (uint32_t)((warp * 16 + lrow) * AT_STRIDE + acol) * 2;
            ldsm4(qf[0], qf[1], qf[2], qf[3], sQ + qaddr);
            uint32_t kf[4][4];
            #pragma unroll
            for (int kg = 0; kg < 4; ++kg) {
                uint32_t kaddr = (uint32_t)((kg * 16 + lrow) * AT_STRIDE + acol) * 2;
                ldsm4(kf[kg][0], kf[kg][1], kf[kg][2], kf[kg][3], sK + kaddr);
            }
            #pragma unroll
            for (int kg = 0; kg < 4; ++kg)
                #pragma unroll
                for (int o = 0; o < 2; ++o)
                    mma_f16(sacc[kg * 2 + o], qf[0], qf[1], qf[2], qf[3], kf[kg][o], kf[kg][o + 2]);
        }

        int r0loc = warp * 16 + (lane >> 2);
        bool diag = (j0 == q0);
        float mx[2] = { -1e30f, -1e30f };
        #pragma unroll
        for (int nf = 0; nf < 8; nf++) {
            #pragma unroll
            for (int i = 0; i < 4; i++) {
                float v = sacc[nf][i] * 0.125f;
                if (diag) {
                    int col = nf * 8 + (lane & 3) * 2 + (i & 1);
                    int row = r0loc + ((i >> 1) ? 8 : 0);
                    if (col > row) v = -1e30f;
                }
                sacc[nf][i] = v;
                mx[i >> 1] = fmaxf(mx[i >> 1], v);
            }
        }
        #pragma unroll
        for (int o = 1; o < 4; o <<= 1) {
            mx[0] = fmaxf(mx[0], __shfl_xor_sync(0xffffffffu, mx[0], o));
            mx[1] = fmaxf(mx[1], __shfl_xor_sync(0xffffffffu, mx[1], o));
        }
        float fac[2], sum[2] = { 0.f, 0.f };
        #pragma unroll
        for (int j = 0; j < 2; j++) {
            float mnew = fmaxf(m[j], mx[j]);
            fac[j] = __expf(m[j] - mnew);
            m[j] = mnew;
        }
        #pragma unroll
        for (int nf = 0; nf < 8; nf++) {
            #pragma unroll
            for (int i = 0; i < 4; i++) {
                float p = __expf(sacc[nf][i] - m[i >> 1]);
                sacc[nf][i] = p;
                sum[i >> 1] += p;
            }
        }
        #pragma unroll
        for (int o = 1; o < 4; o <<= 1) {
            sum[0] += __shfl_xor_sync(0xffffffffu, sum[0], o);
            sum[1] += __shfl_xor_sync(0xffffffffu, sum[1], o);
        }
        #pragma unroll
        for (int j = 0; j < 2; j++) l[j] = l[j] * fac[j] + sum[j];
        #pragma unroll
        for (int nf = 0; nf < 8; nf++) {
            oacc[nf][0] *= fac[0]; oacc[nf][1] *= fac[0];
            oacc[nf][2] *= fac[1]; oacc[nf][3] *= fac[1];
        }

        #pragma unroll
        for (int t2 = 0; t2 < 4; ++t2) {
            float* p0 = sacc[2 * t2];
            float* p1 = sacc[2 * t2 + 1];
            uint32_t pa[4];
            pa[0] = packh2(p0[0], p0[1]);
            pa[1] = packh2(p0[2], p0[3]);
            pa[2] = packh2(p1[0], p1[1]);
            pa[3] = packh2(p1[2], p1[3]);

            uint32_t vf[4][4];
            #pragma unroll
            for (int nd = 0; nd < 4; ++nd) {
                uint32_t vrow = (uint32_t)(t2 * 16 + ((lane >> 4) << 3) + (lane & 7));
                uint32_t vcol = (uint32_t)(nd * 16 + (((lane >> 3) & 1) << 3));
                uint32_t vaddr = (vrow * AT_STRIDE + vcol) * 2;
                ldsm4t(vf[nd][0], vf[nd][1], vf[nd][2], vf[nd][3], sV + vaddr);
            }
            #pragma unroll
            for (int nd = 0; nd < 4; ++nd)
                #pragma unroll
                for (int o = 0; o < 2; ++o)
                    mma_f16(oacc[nd * 2 + o], pa[0], pa[1], pa[2], pa[3], vf[nd][o], vf[nd][o + 2]);
        }
        __syncthreads();
    }

    float inv0 = 1.f / l[0], inv1 = 1.f / l[1];
    long row0 = (long)(b * Sq_ + q0 + warp * 16 + (lane >> 2));
    long row1 = row0 + 8;
    #pragma unroll
    for (int nf = 0; nf < 8; nf++) {
        int col = h * DHq_ + nf * 8 + (lane & 3) * 2;
        *(__half2*)&O[row0 * Dq_ + col] = __floats2half2_rn(oacc[nf][0] * inv0, oacc[nf][1] * inv0);
        *(__half2*)&O[row1 * Dq_ + col] = __floats2half2_rn(oacc[nf][2] * inv1, oacc[nf][3] * inv1);
    }
}

// ---------------- launcher ----------------
extern "C" void kernel_launch(void* const* d_in, const int* in_sizes, int n_in,
                              void* d_out, int out_size) {
    const int*   x    = (const int*)  d_in[0];
    const float* tok  = (const float*)d_in[1];
    const float* pos  = (const float*)d_in[2];
    const float* Wq   = (const float*)d_in[3];
    const float* bq   = (const float*)d_in[4];
    const float* Wk   = (const float*)d_in[5];
    const float* bk   = (const float*)d_in[6];
    const float* Wv   = (const float*)d_in[7];
    const float* bv   = (const float*)d_in[8];
    const float* Wo   = (const float*)d_in[9];
    const float* bo   = (const float*)d_in[10];
    const float* ln1w = (const float*)d_in[11];
    const float* ln1b = (const float*)d_in[12];
    const float* ln2w = (const float*)d_in[13];
    const float* ln2b = (const float*)d_in[14];
    const float* W1   = (const float*)d_in[15];
    const float* b1   = (const float*)d_in[16];
    const float* W2   = (const float*)d_in[17];
    const float* b2   = (const float*)d_in[18];
    const float* lnfw = (const float*)d_in[19];
    const float* lnfb = (const float*)d_in[20];
    const float* Wout = (const float*)d_in[21];
    const float* bout = (const float*)d_in[22];
    float* out = (float*)d_out;

    float *h;
    f16 *a, *q, *k, *v, *o, *f, *whi;
    cudaGetSymbolAddress((void**)&h, g_h);
    cudaGetSymbolAddress((void**)&a, g_a);
    cudaGetSymbolAddress((void**)&q, g_q);
    cudaGetSymbolAddress((void**)&k, g_k);
    cudaGetSymbolAddress((void**)&v, g_v);
    cudaGetSymbolAddress((void**)&o, g_o);
    cudaGetSymbolAddress((void**)&f, g_f);
    cudaGetSymbolAddress((void**)&whi, g_whi);

    cudaFuncSetAttribute((const void*)gemm_kernel<0,true>,  cudaFuncAttributeMaxDynamicSharedMemorySize, GEMM_SMEM);
    cudaFuncSetAttribute((const void*)gemm_kernel<1,false>, cudaFuncAttributeMaxDynamicSharedMemorySize, GEMM_SMEM);
    cudaFuncSetAttribute((const void*)gemm_kernel<2,false>, cudaFuncAttributeMaxDynamicSharedMemorySize, GEMM_SMEM);
    cudaFuncSetAttribute((const void*)gemm_qkv_kernel, cudaFuncAttributeMaxDynamicSharedMemorySize, GEMM_SMEM);
    cudaFuncSetAttribute((const void*)attn_kernel, cudaFuncAttributeMaxDynamicSharedMemorySize, ATTN_SMEM);

    // ---- weight prep (batched, fp16 1-term) ----
    dim3 tb(32, 8);
    tsplit_sq_kernel<<<dim3(24, 24, 48), tb>>>(Wq, Wk, Wv, Wo, whi);
    tsplit_w1_kernel<<<dim3(Hq_ / 32, 24, 12), tb>>>(W1, whi);
    tsplit_w2_kernel<<<dim3(24, Hq_ / 32, 12), tb>>>(W2, whi);
    tsplit_out_kernel<<<dim3(VPAD_ / 32, 24), tb>>>(Wout, whi);

    embed_kernel<<<Mq_, 256>>>(x, tok, pos, h);

    dim3 gQKV(Dq_ / 64, Mq_ / 128, 3);    // 12 x 32 x 3
    dim3 gD(Dq_ / 64, Mq_ / 128);         // 12 x 32 = 384 blocks: single wave at 3 CTAs/SM
    dim3 gH(Hq_ / 64, Mq_ / 128);         // 48 x 32
    dim3 gVsw(Mq_ / 128, VPAD_ / 64);     // SWAP grid
    dim3 gAtt(Sq_ / 64, NHq_, Bq_);
    const int LNG = Mq_ / 8;

    for (int i = 0; i < Lq_; ++i) {
        size_t off = (size_t)i * LWBLK;
        ln_warp_kernel<<<LNG, 256>>>(h, ln1w + i * Dq_, ln1b + i * Dq_, a);

        gemm_qkv_kernel<<<gQKV, 256, GEMM_SMEM>>>(a, whi + off,
            bq + i * Dq_, bk + i * Dq_, bv + i * Dq_, q, k, v);
        attn_kernel<<<gAtt, 128, ATTN_SMEM>>>(q, k, v, o);

        // proj: residual add in-place into h (single wave, no split-K)
        gemm_kernel<2,false><<<gD, 256, GEMM_SMEM>>>(o, whi + off + 3 * WSQ,
            bo + i * Dq_, h, nullptr, Dq_, Dq_, Dq_);

        ln_warp_kernel<<<LNG, 256>>>(h, ln2w + i * Dq_, ln2b + i * Dq_, a);

        gemm_kernel<1,false><<<gH, 256, GEMM_SMEM>>>(a, whi + off + 4 * WSQ,
            b1 + i * Hq_, nullptr, f, Dq_, Hq_, Hq_);

        // FFN2: residual add in-place into h
        gemm_kernel<2,false><<<gD, 256, GEMM_SMEM>>>(f, whi + off + 4 * WSQ + WSH,
            b2 + i * Dq_, h, nullptr, Hq_, Dq_, Dq_);
    }

    ln_warp_kernel<<<LNG, 256>>>(h, lnfw, lnfb, a);
    gemm_kernel<0,true><<<gVsw, 256, GEMM_SMEM>>>(a, whi + WOUT_OFF,
        bout, out, nullptr, Dq_, VPAD_, Vq_);
}